// round 1
// baseline (speedup 1.0000x reference)
#include <cuda_runtime.h>
#include <math.h>
#include <stdint.h>

// ---------------- problem constants ----------------
#define Dm   1024
#define Tn   2048
#define Bn   2
#define Hn   16
#define HDm  64
#define DFFn 4096
#define Mrows (Bn * Tn)   // 4096

// ---------------- scratch (no allocation allowed) ----------------
__device__ float g_h  [(size_t)Mrows * Dm];        // LN output (reused ln1/ln2)
__device__ float g_qkv[(size_t)Mrows * 3 * Dm];    // QKV
__device__ float g_y  [(size_t)Mrows * Dm];        // attention out
__device__ float g_x1 [(size_t)Mrows * Dm];        // x + attn
__device__ float g_a  [(size_t)Mrows * DFFn];      // gelu(fc1)

// ---------------- LayerNorm: one block per row ----------------
__global__ void ln_kernel(const float* __restrict__ X,
                          const float* __restrict__ gw,
                          const float* __restrict__ bw,
                          float* __restrict__ O)
{
    int row = blockIdx.x;
    int tid = threadIdx.x;                       // 256 threads, 4 floats each
    const float4* xr = (const float4*)(X + (size_t)row * Dm);
    float4 v = xr[tid];
    float s  = v.x + v.y + v.z + v.w;
    float sq = v.x * v.x + v.y * v.y + v.z * v.z + v.w * v.w;
#pragma unroll
    for (int o = 16; o > 0; o >>= 1) {
        s  += __shfl_xor_sync(0xffffffffu, s,  o);
        sq += __shfl_xor_sync(0xffffffffu, sq, o);
    }
    __shared__ float ws[8], wq[8];
    int wid = tid >> 5, lane = tid & 31;
    if (lane == 0) { ws[wid] = s; wq[wid] = sq; }
    __syncthreads();
    float ts = 0.f, tq = 0.f;
#pragma unroll
    for (int i = 0; i < 8; i++) { ts += ws[i]; tq += wq[i]; }
    float mean = ts * (1.0f / Dm);
    float var  = tq * (1.0f / Dm) - mean * mean;
    float rstd = rsqrtf(var + 1e-5f);
    float4 g4 = ((const float4*)gw)[tid];
    float4 b4 = ((const float4*)bw)[tid];
    float4 o4;
    o4.x = (v.x - mean) * rstd * g4.x + b4.x;
    o4.y = (v.y - mean) * rstd * g4.y + b4.y;
    o4.z = (v.z - mean) * rstd * g4.z + b4.z;
    o4.w = (v.w - mean) * rstd * g4.w + b4.w;
    ((float4*)(O + (size_t)row * Dm))[tid] = o4;
}

// ---------------- SGEMM 128x128x8, 256 threads, 8x8 per thread ----------------
// C = A[MxK] @ B[KxN]  (+ R residual) (optionally exact GELU)
__device__ __forceinline__ float gelu_exact(float x) {
    return 0.5f * x * (1.0f + erff(x * 0.70710678118654752f));
}

template <int GELU, int RESID>
__global__ __launch_bounds__(256, 2)
void sgemm_k(const float* __restrict__ A, const float* __restrict__ B,
             const float* __restrict__ R, float* __restrict__ C,
             int M, int N, int K)
{
    const int BM = 128, BN = 128, BK = 8;
    __shared__ float As[BK][BM + 4];
    __shared__ float Bs[BK][BN + 4];

    int tid = threadIdx.x;
    int tx = tid & 15;         // 0..15 -> col groups
    int ty = tid >> 4;         // 0..15 -> row groups (8 rows each)
    int bx = blockIdx.x;       // N tiles
    int by = blockIdx.y;       // M tiles

    // load indices
    int arow = tid >> 1;             // 0..127
    int acol = (tid & 1) * 4;        // 0 or 4
    int brow = tid >> 5;             // 0..7
    int bcol = (tid & 31) * 4;       // 0..124

    const float* Ag = A + ((size_t)(by * BM + arow)) * K + acol;
    const float* Bg = B + (size_t)brow * N + bx * BN + bcol;

    float acc[8][8];
#pragma unroll
    for (int i = 0; i < 8; i++)
#pragma unroll
        for (int j = 0; j < 8; j++) acc[i][j] = 0.f;

    for (int k0 = 0; k0 < K; k0 += BK) {
        float4 av = *(const float4*)(Ag + k0);
        As[acol + 0][arow] = av.x;
        As[acol + 1][arow] = av.y;
        As[acol + 2][arow] = av.z;
        As[acol + 3][arow] = av.w;
        float4 bv = *(const float4*)(Bg + (size_t)k0 * N);
        *(float4*)&Bs[brow][bcol] = bv;
        __syncthreads();

#pragma unroll
        for (int kk = 0; kk < BK; kk++) {
            float4 a0 = *(const float4*)&As[kk][ty * 8];
            float4 a1 = *(const float4*)&As[kk][ty * 8 + 4];
            float4 b0 = *(const float4*)&Bs[kk][tx * 4];
            float4 b1 = *(const float4*)&Bs[kk][tx * 4 + 64];
            float a[8] = {a0.x, a0.y, a0.z, a0.w, a1.x, a1.y, a1.z, a1.w};
            float b[8] = {b0.x, b0.y, b0.z, b0.w, b1.x, b1.y, b1.z, b1.w};
#pragma unroll
            for (int i = 0; i < 8; i++)
#pragma unroll
                for (int j = 0; j < 8; j++)
                    acc[i][j] = fmaf(a[i], b[j], acc[i][j]);
        }
        __syncthreads();
    }

    // epilogue: rows by*128 + ty*8 + i ; cols bx*128 + (tx*4 .. / 64+tx*4 ..)
#pragma unroll
    for (int i = 0; i < 8; i++) {
        size_t row = (size_t)(by * BM + ty * 8 + i);
        float* cp = C + row * N + bx * BN;
        float4 v0, v1;
        v0.x = acc[i][0]; v0.y = acc[i][1]; v0.z = acc[i][2]; v0.w = acc[i][3];
        v1.x = acc[i][4]; v1.y = acc[i][5]; v1.z = acc[i][6]; v1.w = acc[i][7];
        if (GELU) {
            v0.x = gelu_exact(v0.x); v0.y = gelu_exact(v0.y);
            v0.z = gelu_exact(v0.z); v0.w = gelu_exact(v0.w);
            v1.x = gelu_exact(v1.x); v1.y = gelu_exact(v1.y);
            v1.z = gelu_exact(v1.z); v1.w = gelu_exact(v1.w);
        }
        if (RESID) {
            const float* rp = R + row * N + bx * BN;
            float4 r0 = *(const float4*)(rp + tx * 4);
            float4 r1 = *(const float4*)(rp + tx * 4 + 64);
            v0.x += r0.x; v0.y += r0.y; v0.z += r0.z; v0.w += r0.w;
            v1.x += r1.x; v1.y += r1.y; v1.z += r1.z; v1.w += r1.w;
        }
        *(float4*)(cp + tx * 4)      = v0;
        *(float4*)(cp + tx * 4 + 64) = v1;
    }
}

// ---------------- Flash attention (fp32), BQ=64, hd=64 ----------------
// QKV layout: [B*T, 3*1024]; q at col h*64, k at 1024+h*64, v at 2048+h*64
#define ATTN_SMEM_FLOATS (3 * 64 * 65 + 64 * 64)

__global__ __launch_bounds__(256, 3)
void attn_kernel(const float* __restrict__ QKV, float* __restrict__ Y)
{
    extern __shared__ float sm[];
    float* Qt = sm;                 // Qt[d*65 + q]
    float* Kt = Qt + 64 * 65;       // Kt[d*65 + k]
    float* Pt = Kt + 64 * 65;       // Pt[k*65 + q]
    float* Vs = Pt + 64 * 65;       // Vs[k*64 + c]

    int tid = threadIdx.x;
    int tx = tid & 15, ty = tid >> 4;
    int qt = blockIdx.x;            // 0..31
    int h  = blockIdx.y;            // 0..15
    int b  = blockIdx.z;            // 0..1
    int q0 = qt * 64;
    const int C3 = 3 * Dm;
    const float* base = QKV + (size_t)b * Tn * C3;

    // load Q tile transposed
    for (int i = tid; i < 64 * 16; i += 256) {
        int r = i >> 4, cg = (i & 15) * 4;
        float4 v = *(const float4*)(base + (size_t)(q0 + r) * C3 + h * 64 + cg);
        Qt[(cg + 0) * 65 + r] = v.x;
        Qt[(cg + 1) * 65 + r] = v.y;
        Qt[(cg + 2) * 65 + r] = v.z;
        Qt[(cg + 3) * 65 + r] = v.w;
    }

    float m[4], l[4], o[4][4];
#pragma unroll
    for (int i = 0; i < 4; i++) {
        m[i] = -1e30f; l[i] = 0.f;
#pragma unroll
        for (int j = 0; j < 4; j++) o[i][j] = 0.f;
    }

    int nkt = qt + 1;
    for (int kt = 0; kt < nkt; kt++) {
        int k0 = kt * 64;
        __syncthreads();   // protect Kt/Vs/Pt from previous iteration readers
        for (int i = tid; i < 64 * 16; i += 256) {
            int r = i >> 4, cg = (i & 15) * 4;
            float4 kv = *(const float4*)(base + (size_t)(k0 + r) * C3 + 1024 + h * 64 + cg);
            Kt[(cg + 0) * 65 + r] = kv.x;
            Kt[(cg + 1) * 65 + r] = kv.y;
            Kt[(cg + 2) * 65 + r] = kv.z;
            Kt[(cg + 3) * 65 + r] = kv.w;
            float4 vv = *(const float4*)(base + (size_t)(k0 + r) * C3 + 2048 + h * 64 + cg);
            *(float4*)&Vs[r * 64 + cg] = vv;
        }
        __syncthreads();

        // S = Q K^T (4x4 register tile)
        float s[4][4];
#pragma unroll
        for (int i = 0; i < 4; i++)
#pragma unroll
            for (int j = 0; j < 4; j++) s[i][j] = 0.f;

        for (int d = 0; d < 64; d++) {
            float a0 = Qt[d * 65 + ty * 4 + 0];
            float a1 = Qt[d * 65 + ty * 4 + 1];
            float a2 = Qt[d * 65 + ty * 4 + 2];
            float a3 = Qt[d * 65 + ty * 4 + 3];
            float b0 = Kt[d * 65 + tx * 4 + 0];
            float b1 = Kt[d * 65 + tx * 4 + 1];
            float b2 = Kt[d * 65 + tx * 4 + 2];
            float b3 = Kt[d * 65 + tx * 4 + 3];
            s[0][0] = fmaf(a0, b0, s[0][0]); s[0][1] = fmaf(a0, b1, s[0][1]);
            s[0][2] = fmaf(a0, b2, s[0][2]); s[0][3] = fmaf(a0, b3, s[0][3]);
            s[1][0] = fmaf(a1, b0, s[1][0]); s[1][1] = fmaf(a1, b1, s[1][1]);
            s[1][2] = fmaf(a1, b2, s[1][2]); s[1][3] = fmaf(a1, b3, s[1][3]);
            s[2][0] = fmaf(a2, b0, s[2][0]); s[2][1] = fmaf(a2, b1, s[2][1]);
            s[2][2] = fmaf(a2, b2, s[2][2]); s[2][3] = fmaf(a2, b3, s[2][3]);
            s[3][0] = fmaf(a3, b0, s[3][0]); s[3][1] = fmaf(a3, b1, s[3][1]);
            s[3][2] = fmaf(a3, b2, s[3][2]); s[3][3] = fmaf(a3, b3, s[3][3]);
        }

        const float scale = 0.125f;   // 1/sqrt(64)
#pragma unroll
        for (int i = 0; i < 4; i++)
#pragma unroll
            for (int j = 0; j < 4; j++) s[i][j] *= scale;

        if (kt == qt) {  // diagonal tile: causal mask
#pragma unroll
            for (int i = 0; i < 4; i++)
#pragma unroll
                for (int j = 0; j < 4; j++)
                    if (tx * 4 + j > ty * 4 + i) s[i][j] = -1e30f;
        }

        // online softmax per row (reduce over the 16 tx lanes)
#pragma unroll
        for (int i = 0; i < 4; i++) {
            float rm = fmaxf(fmaxf(s[i][0], s[i][1]), fmaxf(s[i][2], s[i][3]));
#pragma unroll
            for (int off = 8; off >= 1; off >>= 1)
                rm = fmaxf(rm, __shfl_xor_sync(0xffffffffu, rm, off));
            float mn = fmaxf(m[i], rm);
            float alpha = __expf(m[i] - mn);
            m[i] = mn;
            float rs = 0.f;
#pragma unroll
            for (int j = 0; j < 4; j++) {
                s[i][j] = __expf(s[i][j] - mn);
                rs += s[i][j];
            }
#pragma unroll
            for (int off = 8; off >= 1; off >>= 1)
                rs += __shfl_xor_sync(0xffffffffu, rs, off);
            l[i] = l[i] * alpha + rs;
#pragma unroll
            for (int j = 0; j < 4; j++) o[i][j] *= alpha;
        }

        // write P transposed
#pragma unroll
        for (int j = 0; j < 4; j++)
#pragma unroll
            for (int i = 0; i < 4; i++)
                Pt[(tx * 4 + j) * 65 + ty * 4 + i] = s[i][j];
        __syncthreads();

        // O += P @ V
        for (int k = 0; k < 64; k++) {
            float a0 = Pt[k * 65 + ty * 4 + 0];
            float a1 = Pt[k * 65 + ty * 4 + 1];
            float a2 = Pt[k * 65 + ty * 4 + 2];
            float a3 = Pt[k * 65 + ty * 4 + 3];
            float b0 = Vs[k * 64 + tx * 4 + 0];
            float b1 = Vs[k * 64 + tx * 4 + 1];
            float b2 = Vs[k * 64 + tx * 4 + 2];
            float b3 = Vs[k * 64 + tx * 4 + 3];
            o[0][0] = fmaf(a0, b0, o[0][0]); o[0][1] = fmaf(a0, b1, o[0][1]);
            o[0][2] = fmaf(a0, b2, o[0][2]); o[0][3] = fmaf(a0, b3, o[0][3]);
            o[1][0] = fmaf(a1, b0, o[1][0]); o[1][1] = fmaf(a1, b1, o[1][1]);
            o[1][2] = fmaf(a1, b2, o[1][2]); o[1][3] = fmaf(a1, b3, o[1][3]);
            o[2][0] = fmaf(a2, b0, o[2][0]); o[2][1] = fmaf(a2, b1, o[2][1]);
            o[2][2] = fmaf(a2, b2, o[2][2]); o[2][3] = fmaf(a2, b3, o[2][3]);
            o[3][0] = fmaf(a3, b0, o[3][0]); o[3][1] = fmaf(a3, b1, o[3][1]);
            o[3][2] = fmaf(a3, b2, o[3][2]); o[3][3] = fmaf(a3, b3, o[3][3]);
        }
    }

    // epilogue: Y[(b*T + q)*1024 + h*64 + c] = o / l
    float* yb = Y + ((size_t)b * Tn + q0) * Dm + h * 64;
#pragma unroll
    for (int i = 0; i < 4; i++) {
        float inv = 1.0f / l[i];
#pragma unroll
        for (int j = 0; j < 4; j++)
            yb[(size_t)(ty * 4 + i) * Dm + tx * 4 + j] = o[i][j] * inv;
    }
}

// ---------------- launch ----------------
extern "C" void kernel_launch(void* const* d_in, const int* in_sizes, int n_in,
                              void* d_out, int out_size)
{
    (void)in_sizes; (void)n_in; (void)out_size;
    const float* x     = (const float*)d_in[0];
    const float* Wqkv  = (const float*)d_in[1];
    const float* Wproj = (const float*)d_in[2];
    const float* Wfc1  = (const float*)d_in[3];
    const float* Wfc2  = (const float*)d_in[4];
    const float* ln1g  = (const float*)d_in[5];
    const float* ln1b  = (const float*)d_in[6];
    const float* ln2g  = (const float*)d_in[7];
    const float* ln2b  = (const float*)d_in[8];
    float* out = (float*)d_out;

    float *h, *qkv, *y, *x1, *a;
    cudaGetSymbolAddress((void**)&h,   g_h);
    cudaGetSymbolAddress((void**)&qkv, g_qkv);
    cudaGetSymbolAddress((void**)&y,   g_y);
    cudaGetSymbolAddress((void**)&x1,  g_x1);
    cudaGetSymbolAddress((void**)&a,   g_a);

    const int attn_smem = ATTN_SMEM_FLOATS * (int)sizeof(float);
    cudaFuncSetAttribute(attn_kernel, cudaFuncAttributeMaxDynamicSharedMemorySize, attn_smem);

    // 1) ln1
    ln_kernel<<<Mrows, 256>>>(x, ln1g, ln1b, h);
    // 2) qkv = h @ W_qkv   [4096 x 3072]
    sgemm_k<0, 0><<<dim3(3 * Dm / 128, Mrows / 128), 256>>>(h, Wqkv, nullptr, qkv, Mrows, 3 * Dm, Dm);
    // 3) attention
    attn_kernel<<<dim3(Tn / 64, Hn, Bn), 256, attn_smem>>>(qkv, y);
    // 4) x1 = x + y @ W_proj
    sgemm_k<0, 1><<<dim3(Dm / 128, Mrows / 128), 256>>>(y, Wproj, x, x1, Mrows, Dm, Dm);
    // 5) ln2
    ln_kernel<<<Mrows, 256>>>(x1, ln2g, ln2b, h);
    // 6) a = gelu(h @ W_fc1)   [4096 x 4096]
    sgemm_k<1, 0><<<dim3(DFFn / 128, Mrows / 128), 256>>>(h, Wfc1, nullptr, a, Mrows, DFFn, Dm);
    // 7) out = x1 + a @ W_fc2
    sgemm_k<0, 1><<<dim3(Dm / 128, Mrows / 128), 256>>>(a, Wfc2, x1, out, Mrows, Dm, DFFn);
}

// round 2
// speedup vs baseline: 1.7421x; 1.7421x over previous
#include <cuda_runtime.h>
#include <math.h>
#include <stdint.h>

// ---------------- problem constants ----------------
#define Dm   1024
#define Tn   2048
#define Bn   2
#define Hn   16
#define HDm  64
#define DFFn 4096
#define Mrows (Bn * Tn)   // 4096

// ---------------- scratch (no allocation allowed) ----------------
__device__ float g_h  [(size_t)Mrows * Dm];        // LN output (reused ln1/ln2)
__device__ float g_qkv[(size_t)Mrows * 3 * Dm];    // QKV
__device__ float g_y  [(size_t)Mrows * Dm];        // attention out
__device__ float g_x1 [(size_t)Mrows * Dm];        // x + attn
__device__ float g_a  [(size_t)Mrows * DFFn];      // gelu(fc1)

// ---------------- helpers ----------------
__device__ __forceinline__ float to_tf32(float x) {
    uint32_t u;
    asm("cvt.rna.tf32.f32 %0, %1;" : "=r"(u) : "f"(x));
    return __uint_as_float(u);
}

__device__ __forceinline__ void mma_tf32(float* c,
                                         uint32_t a0, uint32_t a1, uint32_t a2, uint32_t a3,
                                         uint32_t b0, uint32_t b1) {
    asm volatile(
        "mma.sync.aligned.m16n8k8.row.col.f32.tf32.tf32.f32 "
        "{%0,%1,%2,%3}, {%4,%5,%6,%7}, {%8,%9}, {%0,%1,%2,%3};"
        : "+f"(c[0]), "+f"(c[1]), "+f"(c[2]), "+f"(c[3])
        : "r"(a0), "r"(a1), "r"(a2), "r"(a3), "r"(b0), "r"(b1));
}

__device__ __forceinline__ float gelu_exact(float x) {
    return 0.5f * x * (1.0f + erff(x * 0.70710678118654752f));
}

// ---------------- LayerNorm: one block per row ----------------
__global__ void ln_kernel(const float* __restrict__ X,
                          const float* __restrict__ gw,
                          const float* __restrict__ bw,
                          float* __restrict__ O)
{
    int row = blockIdx.x;
    int tid = threadIdx.x;                       // 256 threads, 4 floats each
    const float4* xr = (const float4*)(X + (size_t)row * Dm);
    float4 v = xr[tid];
    float s  = v.x + v.y + v.z + v.w;
    float sq = v.x * v.x + v.y * v.y + v.z * v.z + v.w * v.w;
#pragma unroll
    for (int o = 16; o > 0; o >>= 1) {
        s  += __shfl_xor_sync(0xffffffffu, s,  o);
        sq += __shfl_xor_sync(0xffffffffu, sq, o);
    }
    __shared__ float ws[8], wq[8];
    int wid = tid >> 5, lane = tid & 31;
    if (lane == 0) { ws[wid] = s; wq[wid] = sq; }
    __syncthreads();
    float ts = 0.f, tq = 0.f;
#pragma unroll
    for (int i = 0; i < 8; i++) { ts += ws[i]; tq += wq[i]; }
    float mean = ts * (1.0f / Dm);
    float var  = tq * (1.0f / Dm) - mean * mean;
    float rstd = rsqrtf(var + 1e-5f);
    float4 g4 = ((const float4*)gw)[tid];
    float4 b4 = ((const float4*)bw)[tid];
    float4 o4;
    o4.x = (v.x - mean) * rstd * g4.x + b4.x;
    o4.y = (v.y - mean) * rstd * g4.y + b4.y;
    o4.z = (v.z - mean) * rstd * g4.z + b4.z;
    o4.w = (v.w - mean) * rstd * g4.w + b4.w;
    ((float4*)(O + (size_t)row * Dm))[tid] = o4;
}

// ---------------- TF32 tensor-core GEMM ----------------
// C = A[MxK] @ B[KxN]  (+R residual) (optional exact GELU)
// Block tile 128x128, BK=16, 4 warps (2x2), warp tile 64x64.
template <int GELU, int RESID>
__global__ __launch_bounds__(128, 2)
void mma_gemm(const float* __restrict__ A, const float* __restrict__ B,
              const float* __restrict__ R, float* __restrict__ C,
              int M, int N, int K)
{
    __shared__ float As[128][20];   // [m][k], stride 20 -> conflict-free frag loads
    __shared__ float Bs[16][136];   // [k][n], stride 136 (== 8 mod 32) -> conflict-free

    const int tid  = threadIdx.x;
    const int lane = tid & 31;
    const int warp = tid >> 5;
    const int wm = warp & 1;        // 2 warps along M
    const int wn = warp >> 1;       // 2 warps along N
    const int g  = lane >> 2;       // 0..7
    const int qk = lane & 3;        // 0..3
    const int bx = blockIdx.x, by = blockIdx.y;

    const float* Ag = A + (size_t)(by * 128 + tid) * K;            // one row per thread
    const float* Bg = B + (size_t)(warp * 4) * N + bx * 128 + lane * 4;

    float acc[4][8][4];
#pragma unroll
    for (int mf = 0; mf < 4; mf++)
#pragma unroll
        for (int nf = 0; nf < 8; nf++)
#pragma unroll
            for (int r = 0; r < 4; r++) acc[mf][nf][r] = 0.f;

    float4 pa[4], pb[4];
#pragma unroll
    for (int i = 0; i < 4; i++) pa[i] = *(const float4*)(Ag + i * 4);
#pragma unroll
    for (int j = 0; j < 4; j++) pb[j] = *(const float4*)(Bg + (size_t)j * N);

    const int nIter = K / 16;
    for (int it = 0; it < nIter; it++) {
        // fill smem from prefetch regs (rounded to tf32 once, here)
#pragma unroll
        for (int i = 0; i < 4; i++) {
            float4 v = pa[i];
            v.x = to_tf32(v.x); v.y = to_tf32(v.y);
            v.z = to_tf32(v.z); v.w = to_tf32(v.w);
            *(float4*)&As[tid][i * 4] = v;
        }
#pragma unroll
        for (int j = 0; j < 4; j++) {
            float4 v = pb[j];
            v.x = to_tf32(v.x); v.y = to_tf32(v.y);
            v.z = to_tf32(v.z); v.w = to_tf32(v.w);
            *(float4*)&Bs[warp * 4 + j][lane * 4] = v;
        }
        __syncthreads();

        if (it + 1 < nIter) {
            int k0 = (it + 1) * 16;
#pragma unroll
            for (int i = 0; i < 4; i++) pa[i] = *(const float4*)(Ag + k0 + i * 4);
#pragma unroll
            for (int j = 0; j < 4; j++) pb[j] = *(const float4*)(Bg + (size_t)(k0 + j) * N);
        }

#pragma unroll
        for (int ks = 0; ks < 2; ks++) {
            const int kc = ks * 8 + qk;
            uint32_t af[4][4];
#pragma unroll
            for (int mf = 0; mf < 4; mf++) {
                int r0 = wm * 64 + mf * 16 + g;
                af[mf][0] = __float_as_uint(As[r0][kc]);
                af[mf][1] = __float_as_uint(As[r0 + 8][kc]);
                af[mf][2] = __float_as_uint(As[r0][kc + 4]);
                af[mf][3] = __float_as_uint(As[r0 + 8][kc + 4]);
            }
            uint32_t bf[8][2];
#pragma unroll
            for (int nf = 0; nf < 8; nf++) {
                int n0 = wn * 64 + nf * 8 + g;
                bf[nf][0] = __float_as_uint(Bs[kc][n0]);
                bf[nf][1] = __float_as_uint(Bs[kc + 4][n0]);
            }
#pragma unroll
            for (int mf = 0; mf < 4; mf++)
#pragma unroll
                for (int nf = 0; nf < 8; nf++)
                    mma_tf32(acc[mf][nf], af[mf][0], af[mf][1], af[mf][2], af[mf][3],
                             bf[nf][0], bf[nf][1]);
        }
        __syncthreads();
    }

    // epilogue
#pragma unroll
    for (int mf = 0; mf < 4; mf++) {
        int r0 = by * 128 + wm * 64 + mf * 16 + g;
#pragma unroll
        for (int nf = 0; nf < 8; nf++) {
            int c0 = bx * 128 + wn * 64 + nf * 8 + qk * 2;
            float2 v0, v1;
            v0.x = acc[mf][nf][0]; v0.y = acc[mf][nf][1];   // row r0
            v1.x = acc[mf][nf][2]; v1.y = acc[mf][nf][3];   // row r0+8
            if (GELU) {
                v0.x = gelu_exact(v0.x); v0.y = gelu_exact(v0.y);
                v1.x = gelu_exact(v1.x); v1.y = gelu_exact(v1.y);
            }
            if (RESID) {
                float2 r0v = *(const float2*)(R + (size_t)r0 * N + c0);
                float2 r1v = *(const float2*)(R + (size_t)(r0 + 8) * N + c0);
                v0.x += r0v.x; v0.y += r0v.y;
                v1.x += r1v.x; v1.y += r1v.y;
            }
            *(float2*)(C + (size_t)r0 * N + c0)       = v0;
            *(float2*)(C + (size_t)(r0 + 8) * N + c0) = v1;
        }
    }
}

// ---------------- Flash attention (fp32), BQ=64, hd=64 ----------------
// QKV layout: [B*T, 3*1024]; q at col h*64, k at 1024+h*64, v at 2048+h*64
#define ATTN_SMEM_FLOATS (3 * 64 * 65 + 64 * 64)

__global__ __launch_bounds__(256, 3)
void attn_kernel(const float* __restrict__ QKV, float* __restrict__ Y)
{
    extern __shared__ float sm[];
    float* Qt = sm;                 // Qt[d*65 + q]
    float* Kt = Qt + 64 * 65;       // Kt[d*65 + k]
    float* Pt = Kt + 64 * 65;       // Pt[k*65 + q]
    float* Vs = Pt + 64 * 65;       // Vs[k*64 + c]

    int tid = threadIdx.x;
    int tx = tid & 15, ty = tid >> 4;
    int qt = blockIdx.x;            // 0..31
    int h  = blockIdx.y;            // 0..15
    int b  = blockIdx.z;            // 0..1
    int q0 = qt * 64;
    const int C3 = 3 * Dm;
    const float* base = QKV + (size_t)b * Tn * C3;

    // load Q tile transposed
    for (int i = tid; i < 64 * 16; i += 256) {
        int r = i >> 4, cg = (i & 15) * 4;
        float4 v = *(const float4*)(base + (size_t)(q0 + r) * C3 + h * 64 + cg);
        Qt[(cg + 0) * 65 + r] = v.x;
        Qt[(cg + 1) * 65 + r] = v.y;
        Qt[(cg + 2) * 65 + r] = v.z;
        Qt[(cg + 3) * 65 + r] = v.w;
    }

    float m[4], l[4], o[4][4];
#pragma unroll
    for (int i = 0; i < 4; i++) {
        m[i] = -1e30f; l[i] = 0.f;
#pragma unroll
        for (int j = 0; j < 4; j++) o[i][j] = 0.f;
    }

    int nkt = qt + 1;
    for (int kt = 0; kt < nkt; kt++) {
        int k0 = kt * 64;
        __syncthreads();
        for (int i = tid; i < 64 * 16; i += 256) {
            int r = i >> 4, cg = (i & 15) * 4;
            float4 kv = *(const float4*)(base + (size_t)(k0 + r) * C3 + 1024 + h * 64 + cg);
            Kt[(cg + 0) * 65 + r] = kv.x;
            Kt[(cg + 1) * 65 + r] = kv.y;
            Kt[(cg + 2) * 65 + r] = kv.z;
            Kt[(cg + 3) * 65 + r] = kv.w;
            float4 vv = *(const float4*)(base + (size_t)(k0 + r) * C3 + 2048 + h * 64 + cg);
            *(float4*)&Vs[r * 64 + cg] = vv;
        }
        __syncthreads();

        float s[4][4];
#pragma unroll
        for (int i = 0; i < 4; i++)
#pragma unroll
            for (int j = 0; j < 4; j++) s[i][j] = 0.f;

        for (int d = 0; d < 64; d++) {
            float a0 = Qt[d * 65 + ty * 4 + 0];
            float a1 = Qt[d * 65 + ty * 4 + 1];
            float a2 = Qt[d * 65 + ty * 4 + 2];
            float a3 = Qt[d * 65 + ty * 4 + 3];
            float b0 = Kt[d * 65 + tx * 4 + 0];
            float b1 = Kt[d * 65 + tx * 4 + 1];
            float b2 = Kt[d * 65 + tx * 4 + 2];
            float b3 = Kt[d * 65 + tx * 4 + 3];
            s[0][0] = fmaf(a0, b0, s[0][0]); s[0][1] = fmaf(a0, b1, s[0][1]);
            s[0][2] = fmaf(a0, b2, s[0][2]); s[0][3] = fmaf(a0, b3, s[0][3]);
            s[1][0] = fmaf(a1, b0, s[1][0]); s[1][1] = fmaf(a1, b1, s[1][1]);
            s[1][2] = fmaf(a1, b2, s[1][2]); s[1][3] = fmaf(a1, b3, s[1][3]);
            s[2][0] = fmaf(a2, b0, s[2][0]); s[2][1] = fmaf(a2, b1, s[2][1]);
            s[2][2] = fmaf(a2, b2, s[2][2]); s[2][3] = fmaf(a2, b3, s[2][3]);
            s[3][0] = fmaf(a3, b0, s[3][0]); s[3][1] = fmaf(a3, b1, s[3][1]);
            s[3][2] = fmaf(a3, b2, s[3][2]); s[3][3] = fmaf(a3, b3, s[3][3]);
        }

        const float scale = 0.125f;   // 1/sqrt(64)
#pragma unroll
        for (int i = 0; i < 4; i++)
#pragma unroll
            for (int j = 0; j < 4; j++) s[i][j] *= scale;

        if (kt == qt) {
#pragma unroll
            for (int i = 0; i < 4; i++)
#pragma unroll
                for (int j = 0; j < 4; j++)
                    if (tx * 4 + j > ty * 4 + i) s[i][j] = -1e30f;
        }

#pragma unroll
        for (int i = 0; i < 4; i++) {
            float rm = fmaxf(fmaxf(s[i][0], s[i][1]), fmaxf(s[i][2], s[i][3]));
#pragma unroll
            for (int off = 8; off >= 1; off >>= 1)
                rm = fmaxf(rm, __shfl_xor_sync(0xffffffffu, rm, off));
            float mn = fmaxf(m[i], rm);
            float alpha = __expf(m[i] - mn);
            m[i] = mn;
            float rs = 0.f;
#pragma unroll
            for (int j = 0; j < 4; j++) {
                s[i][j] = __expf(s[i][j] - mn);
                rs += s[i][j];
            }
#pragma unroll
            for (int off = 8; off >= 1; off >>= 1)
                rs += __shfl_xor_sync(0xffffffffu, rs, off);
            l[i] = l[i] * alpha + rs;
#pragma unroll
            for (int j = 0; j < 4; j++) o[i][j] *= alpha;
        }

#pragma unroll
        for (int j = 0; j < 4; j++)
#pragma unroll
            for (int i = 0; i < 4; i++)
                Pt[(tx * 4 + j) * 65 + ty * 4 + i] = s[i][j];
        __syncthreads();

        for (int k = 0; k < 64; k++) {
            float a0 = Pt[k * 65 + ty * 4 + 0];
            float a1 = Pt[k * 65 + ty * 4 + 1];
            float a2 = Pt[k * 65 + ty * 4 + 2];
            float a3 = Pt[k * 65 + ty * 4 + 3];
            float b0 = Vs[k * 64 + tx * 4 + 0];
            float b1 = Vs[k * 64 + tx * 4 + 1];
            float b2 = Vs[k * 64 + tx * 4 + 2];
            float b3 = Vs[k * 64 + tx * 4 + 3];
            o[0][0] = fmaf(a0, b0, o[0][0]); o[0][1] = fmaf(a0, b1, o[0][1]);
            o[0][2] = fmaf(a0, b2, o[0][2]); o[0][3] = fmaf(a0, b3, o[0][3]);
            o[1][0] = fmaf(a1, b0, o[1][0]); o[1][1] = fmaf(a1, b1, o[1][1]);
            o[1][2] = fmaf(a1, b2, o[1][2]); o[1][3] = fmaf(a1, b3, o[1][3]);
            o[2][0] = fmaf(a2, b0, o[2][0]); o[2][1] = fmaf(a2, b1, o[2][1]);
            o[2][2] = fmaf(a2, b2, o[2][2]); o[2][3] = fmaf(a2, b3, o[2][3]);
            o[3][0] = fmaf(a3, b0, o[3][0]); o[3][1] = fmaf(a3, b1, o[3][1]);
            o[3][2] = fmaf(a3, b2, o[3][2]); o[3][3] = fmaf(a3, b3, o[3][3]);
        }
    }

    float* yb = Y + ((size_t)b * Tn + q0) * Dm + h * 64;
#pragma unroll
    for (int i = 0; i < 4; i++) {
        float inv = 1.0f / l[i];
#pragma unroll
        for (int j = 0; j < 4; j++)
            yb[(size_t)(ty * 4 + i) * Dm + tx * 4 + j] = o[i][j] * inv;
    }
}

// ---------------- launch ----------------
extern "C" void kernel_launch(void* const* d_in, const int* in_sizes, int n_in,
                              void* d_out, int out_size)
{
    (void)in_sizes; (void)n_in; (void)out_size;
    const float* x     = (const float*)d_in[0];
    const float* Wqkv  = (const float*)d_in[1];
    const float* Wproj = (const float*)d_in[2];
    const float* Wfc1  = (const float*)d_in[3];
    const float* Wfc2  = (const float*)d_in[4];
    const float* ln1g  = (const float*)d_in[5];
    const float* ln1b  = (const float*)d_in[6];
    const float* ln2g  = (const float*)d_in[7];
    const float* ln2b  = (const float*)d_in[8];
    float* out = (float*)d_out;

    float *h, *qkv, *y, *x1, *a;
    cudaGetSymbolAddress((void**)&h,   g_h);
    cudaGetSymbolAddress((void**)&qkv, g_qkv);
    cudaGetSymbolAddress((void**)&y,   g_y);
    cudaGetSymbolAddress((void**)&x1,  g_x1);
    cudaGetSymbolAddress((void**)&a,   g_a);

    const int attn_smem = ATTN_SMEM_FLOATS * (int)sizeof(float);
    cudaFuncSetAttribute(attn_kernel, cudaFuncAttributeMaxDynamicSharedMemorySize, attn_smem);

    // 1) ln1
    ln_kernel<<<Mrows, 256>>>(x, ln1g, ln1b, h);
    // 2) qkv = h @ W_qkv   [4096 x 3072], K=1024
    mma_gemm<0, 0><<<dim3(3 * Dm / 128, Mrows / 128), 128>>>(h, Wqkv, nullptr, qkv, Mrows, 3 * Dm, Dm);
    // 3) attention
    attn_kernel<<<dim3(Tn / 64, Hn, Bn), 256, attn_smem>>>(qkv, y);
    // 4) x1 = x + y @ W_proj   [4096 x 1024], K=1024
    mma_gemm<0, 1><<<dim3(Dm / 128, Mrows / 128), 128>>>(y, Wproj, x, x1, Mrows, Dm, Dm);
    // 5) ln2
    ln_kernel<<<Mrows, 256>>>(x1, ln2g, ln2b, h);
    // 6) a = gelu(h @ W_fc1)   [4096 x 4096], K=1024
    mma_gemm<1, 0><<<dim3(DFFn / 128, Mrows / 128), 128>>>(h, Wfc1, nullptr, a, Mrows, DFFn, Dm);
    // 7) out = x1 + a @ W_fc2  [4096 x 1024], K=4096
    mma_gemm<0, 1><<<dim3(Dm / 128, Mrows / 128), 128>>>(a, Wfc2, x1, out, Mrows, Dm, DFFn);
}

// round 3
// speedup vs baseline: 1.7518x; 1.0056x over previous
#include <cuda_runtime.h>
#include <math.h>
#include <stdint.h>

// ---------------- problem constants ----------------
#define Dm   1024
#define Tn   2048
#define Bn   2
#define Hn   16
#define HDm  64
#define DFFn 4096
#define Mrows (Bn * Tn)   // 4096

// ---------------- scratch (no allocation allowed) ----------------
__device__ float g_h  [(size_t)Mrows * Dm];        // LN output (reused ln1/ln2)
__device__ float g_qkv[(size_t)Mrows * 3 * Dm];    // QKV
__device__ float g_y  [(size_t)Mrows * Dm];        // attention out
__device__ float g_x1 [(size_t)Mrows * Dm];        // x + attn
__device__ float g_a  [(size_t)Mrows * DFFn];      // gelu(fc1)

// ---------------- helpers ----------------
__device__ __forceinline__ float to_tf32(float x) {
    uint32_t u;
    asm("cvt.rna.tf32.f32 %0, %1;" : "=r"(u) : "f"(x));
    return __uint_as_float(u);
}

__device__ __forceinline__ void mma_tf32(float* c,
                                         uint32_t a0, uint32_t a1, uint32_t a2, uint32_t a3,
                                         uint32_t b0, uint32_t b1) {
    asm volatile(
        "mma.sync.aligned.m16n8k8.row.col.f32.tf32.tf32.f32 "
        "{%0,%1,%2,%3}, {%4,%5,%6,%7}, {%8,%9}, {%0,%1,%2,%3};"
        : "+f"(c[0]), "+f"(c[1]), "+f"(c[2]), "+f"(c[3])
        : "r"(a0), "r"(a1), "r"(a2), "r"(a3), "r"(b0), "r"(b1));
}

__device__ __forceinline__ float gelu_exact(float x) {
    return 0.5f * x * (1.0f + erff(x * 0.70710678118654752f));
}

// ---------------- LayerNorm: one block per row ----------------
__global__ void ln_kernel(const float* __restrict__ X,
                          const float* __restrict__ gw,
                          const float* __restrict__ bw,
                          float* __restrict__ O)
{
    int row = blockIdx.x;
    int tid = threadIdx.x;                       // 256 threads, 4 floats each
    const float4* xr = (const float4*)(X + (size_t)row * Dm);
    float4 v = xr[tid];
    float s  = v.x + v.y + v.z + v.w;
    float sq = v.x * v.x + v.y * v.y + v.z * v.z + v.w * v.w;
#pragma unroll
    for (int o = 16; o > 0; o >>= 1) {
        s  += __shfl_xor_sync(0xffffffffu, s,  o);
        sq += __shfl_xor_sync(0xffffffffu, sq, o);
    }
    __shared__ float ws[8], wq[8];
    int wid = tid >> 5, lane = tid & 31;
    if (lane == 0) { ws[wid] = s; wq[wid] = sq; }
    __syncthreads();
    float ts = 0.f, tq = 0.f;
#pragma unroll
    for (int i = 0; i < 8; i++) { ts += ws[i]; tq += wq[i]; }
    float mean = ts * (1.0f / Dm);
    float var  = tq * (1.0f / Dm) - mean * mean;
    float rstd = rsqrtf(var + 1e-5f);
    float4 g4 = ((const float4*)gw)[tid];
    float4 b4 = ((const float4*)bw)[tid];
    float4 o4;
    o4.x = (v.x - mean) * rstd * g4.x + b4.x;
    o4.y = (v.y - mean) * rstd * g4.y + b4.y;
    o4.z = (v.z - mean) * rstd * g4.z + b4.z;
    o4.w = (v.w - mean) * rstd * g4.w + b4.w;
    ((float4*)(O + (size_t)row * Dm))[tid] = o4;
}

// ---------------- TF32 tensor-core GEMM ----------------
// C = A[MxK] @ B[KxN]  (+R residual) (optional exact GELU)
// Block tile 128x128, BK=16, 4 warps (2x2), warp tile 64x64.
template <int GELU, int RESID>
__global__ __launch_bounds__(128, 2)
void mma_gemm(const float* __restrict__ A, const float* __restrict__ B,
              const float* __restrict__ R, float* __restrict__ C,
              int M, int N, int K)
{
    __shared__ float As[128][20];   // [m][k], stride 20 -> conflict-free frag loads
    __shared__ float Bs[16][136];   // [k][n], stride 136 (== 8 mod 32) -> conflict-free

    const int tid  = threadIdx.x;
    const int lane = tid & 31;
    const int warp = tid >> 5;
    const int wm = warp & 1;        // 2 warps along M
    const int wn = warp >> 1;       // 2 warps along N
    const int g  = lane >> 2;       // 0..7
    const int qk = lane & 3;        // 0..3
    const int bx = blockIdx.x, by = blockIdx.y;

    const float* Ag = A + (size_t)(by * 128 + tid) * K;            // one row per thread
    const float* Bg = B + (size_t)(warp * 4) * N + bx * 128 + lane * 4;

    float acc[4][8][4];
#pragma unroll
    for (int mf = 0; mf < 4; mf++)
#pragma unroll
        for (int nf = 0; nf < 8; nf++)
#pragma unroll
            for (int r = 0; r < 4; r++) acc[mf][nf][r] = 0.f;

    float4 pa[4], pb[4];
#pragma unroll
    for (int i = 0; i < 4; i++) pa[i] = *(const float4*)(Ag + i * 4);
#pragma unroll
    for (int j = 0; j < 4; j++) pb[j] = *(const float4*)(Bg + (size_t)j * N);

    const int nIter = K / 16;
    for (int it = 0; it < nIter; it++) {
        // fill smem from prefetch regs (rounded to tf32 once, here)
#pragma unroll
        for (int i = 0; i < 4; i++) {
            float4 v = pa[i];
            v.x = to_tf32(v.x); v.y = to_tf32(v.y);
            v.z = to_tf32(v.z); v.w = to_tf32(v.w);
            *(float4*)&As[tid][i * 4] = v;
        }
#pragma unroll
        for (int j = 0; j < 4; j++) {
            float4 v = pb[j];
            v.x = to_tf32(v.x); v.y = to_tf32(v.y);
            v.z = to_tf32(v.z); v.w = to_tf32(v.w);
            *(float4*)&Bs[warp * 4 + j][lane * 4] = v;
        }
        __syncthreads();

        if (it + 1 < nIter) {
            int k0 = (it + 1) * 16;
#pragma unroll
            for (int i = 0; i < 4; i++) pa[i] = *(const float4*)(Ag + k0 + i * 4);
#pragma unroll
            for (int j = 0; j < 4; j++) pb[j] = *(const float4*)(Bg + (size_t)(k0 + j) * N);
        }

#pragma unroll
        for (int ks = 0; ks < 2; ks++) {
            const int kc = ks * 8 + qk;
            uint32_t af[4][4];
#pragma unroll
            for (int mf = 0; mf < 4; mf++) {
                int r0 = wm * 64 + mf * 16 + g;
                af[mf][0] = __float_as_uint(As[r0][kc]);
                af[mf][1] = __float_as_uint(As[r0 + 8][kc]);
                af[mf][2] = __float_as_uint(As[r0][kc + 4]);
                af[mf][3] = __float_as_uint(As[r0 + 8][kc + 4]);
            }
            uint32_t bf[8][2];
#pragma unroll
            for (int nf = 0; nf < 8; nf++) {
                int n0 = wn * 64 + nf * 8 + g;
                bf[nf][0] = __float_as_uint(Bs[kc][n0]);
                bf[nf][1] = __float_as_uint(Bs[kc + 4][n0]);
            }
#pragma unroll
            for (int mf = 0; mf < 4; mf++)
#pragma unroll
                for (int nf = 0; nf < 8; nf++)
                    mma_tf32(acc[mf][nf], af[mf][0], af[mf][1], af[mf][2], af[mf][3],
                             bf[nf][0], bf[nf][1]);
        }
        __syncthreads();
    }

    // epilogue
#pragma unroll
    for (int mf = 0; mf < 4; mf++) {
        int r0 = by * 128 + wm * 64 + mf * 16 + g;
#pragma unroll
        for (int nf = 0; nf < 8; nf++) {
            int c0 = bx * 128 + wn * 64 + nf * 8 + qk * 2;
            float2 v0, v1;
            v0.x = acc[mf][nf][0]; v0.y = acc[mf][nf][1];   // row r0
            v1.x = acc[mf][nf][2]; v1.y = acc[mf][nf][3];   // row r0+8
            if (GELU) {
                v0.x = gelu_exact(v0.x); v0.y = gelu_exact(v0.y);
                v1.x = gelu_exact(v1.x); v1.y = gelu_exact(v1.y);
            }
            if (RESID) {
                float2 r0v = *(const float2*)(R + (size_t)r0 * N + c0);
                float2 r1v = *(const float2*)(R + (size_t)(r0 + 8) * N + c0);
                v0.x += r0v.x; v0.y += r0v.y;
                v1.x += r1v.x; v1.y += r1v.y;
            }
            *(float2*)(C + (size_t)r0 * N + c0)       = v0;
            *(float2*)(C + (size_t)(r0 + 8) * N + c0) = v1;
        }
    }
}

// ---------------- Flash attention (fp32), BQ=64, hd=64 ----------------
// QKV layout: [B*T, 3*1024]; q at col h*64, k at 1024+h*64, v at 2048+h*64
#define ATTN_SMEM_FLOATS (3 * 64 * 65 + 64 * 64)

__global__ __launch_bounds__(256, 3)
void attn_kernel(const float* __restrict__ QKV, float* __restrict__ Y)
{
    extern __shared__ float sm[];
    float* Qt = sm;                 // Qt[d*65 + q]
    float* Kt = Qt + 64 * 65;       // Kt[d*65 + k]
    float* Pt = Kt + 64 * 65;       // Pt[k*65 + q]
    float* Vs = Pt + 64 * 65;       // Vs[k*64 + c]

    int tid = threadIdx.x;
    int tx = tid & 15, ty = tid >> 4;
    int qt = blockIdx.x;            // 0..31
    int h  = blockIdx.y;            // 0..15
    int b  = blockIdx.z;            // 0..1
    int q0 = qt * 64;
    const int C3 = 3 * Dm;
    const float* base = QKV + (size_t)b * Tn * C3;

    // load Q tile transposed
    for (int i = tid; i < 64 * 16; i += 256) {
        int r = i >> 4, cg = (i & 15) * 4;
        float4 v = *(const float4*)(base + (size_t)(q0 + r) * C3 + h * 64 + cg);
        Qt[(cg + 0) * 65 + r] = v.x;
        Qt[(cg + 1) * 65 + r] = v.y;
        Qt[(cg + 2) * 65 + r] = v.z;
        Qt[(cg + 3) * 65 + r] = v.w;
    }

    float m[4], l[4], o[4][4];
#pragma unroll
    for (int i = 0; i < 4; i++) {
        m[i] = -1e30f; l[i] = 0.f;
#pragma unroll
        for (int j = 0; j < 4; j++) o[i][j] = 0.f;
    }

    int nkt = qt + 1;
    for (int kt = 0; kt < nkt; kt++) {
        int k0 = kt * 64;
        __syncthreads();
        for (int i = tid; i < 64 * 16; i += 256) {
            int r = i >> 4, cg = (i & 15) * 4;
            float4 kv = *(const float4*)(base + (size_t)(k0 + r) * C3 + 1024 + h * 64 + cg);
            Kt[(cg + 0) * 65 + r] = kv.x;
            Kt[(cg + 1) * 65 + r] = kv.y;
            Kt[(cg + 2) * 65 + r] = kv.z;
            Kt[(cg + 3) * 65 + r] = kv.w;
            float4 vv = *(const float4*)(base + (size_t)(k0 + r) * C3 + 2048 + h * 64 + cg);
            *(float4*)&Vs[r * 64 + cg] = vv;
        }
        __syncthreads();

        float s[4][4];
#pragma unroll
        for (int i = 0; i < 4; i++)
#pragma unroll
            for (int j = 0; j < 4; j++) s[i][j] = 0.f;

        for (int d = 0; d < 64; d++) {
            float a0 = Qt[d * 65 + ty * 4 + 0];
            float a1 = Qt[d * 65 + ty * 4 + 1];
            float a2 = Qt[d * 65 + ty * 4 + 2];
            float a3 = Qt[d * 65 + ty * 4 + 3];
            float b0 = Kt[d * 65 + tx * 4 + 0];
            float b1 = Kt[d * 65 + tx * 4 + 1];
            float b2 = Kt[d * 65 + tx * 4 + 2];
            float b3 = Kt[d * 65 + tx * 4 + 3];
            s[0][0] = fmaf(a0, b0, s[0][0]); s[0][1] = fmaf(a0, b1, s[0][1]);
            s[0][2] = fmaf(a0, b2, s[0][2]); s[0][3] = fmaf(a0, b3, s[0][3]);
            s[1][0] = fmaf(a1, b0, s[1][0]); s[1][1] = fmaf(a1, b1, s[1][1]);
            s[1][2] = fmaf(a1, b2, s[1][2]); s[1][3] = fmaf(a1, b3, s[1][3]);
            s[2][0] = fmaf(a2, b0, s[2][0]); s[2][1] = fmaf(a2, b1, s[2][1]);
            s[2][2] = fmaf(a2, b2, s[2][2]); s[2][3] = fmaf(a2, b3, s[2][3]);
            s[3][0] = fmaf(a3, b0, s[3][0]); s[3][1] = fmaf(a3, b1, s[3][1]);
            s[3][2] = fmaf(a3, b2, s[3][2]); s[3][3] = fmaf(a3, b3, s[3][3]);
        }

        const float scale = 0.125f;   // 1/sqrt(64)
#pragma unroll
        for (int i = 0; i < 4; i++)
#pragma unroll
            for (int j = 0; j < 4; j++) s[i][j] *= scale;

        if (kt == qt) {
#pragma unroll
            for (int i = 0; i < 4; i++)
#pragma unroll
                for (int j = 0; j < 4; j++)
                    if (tx * 4 + j > ty * 4 + i) s[i][j] = -1e30f;
        }

#pragma unroll
        for (int i = 0; i < 4; i++) {
            float rm = fmaxf(fmaxf(s[i][0], s[i][1]), fmaxf(s[i][2], s[i][3]));
#pragma unroll
            for (int off = 8; off >= 1; off >>= 1)
                rm = fmaxf(rm, __shfl_xor_sync(0xffffffffu, rm, off));
            float mn = fmaxf(m[i], rm);
            float alpha = __expf(m[i] - mn);
            m[i] = mn;
            float rs = 0.f;
#pragma unroll
            for (int j = 0; j < 4; j++) {
                s[i][j] = __expf(s[i][j] - mn);
                rs += s[i][j];
            }
#pragma unroll
            for (int off = 8; off >= 1; off >>= 1)
                rs += __shfl_xor_sync(0xffffffffu, rs, off);
            l[i] = l[i] * alpha + rs;
#pragma unroll
            for (int j = 0; j < 4; j++) o[i][j] *= alpha;
        }

#pragma unroll
        for (int j = 0; j < 4; j++)
#pragma unroll
            for (int i = 0; i < 4; i++)
                Pt[(tx * 4 + j) * 65 + ty * 4 + i] = s[i][j];
        __syncthreads();

        for (int k = 0; k < 64; k++) {
            float a0 = Pt[k * 65 + ty * 4 + 0];
            float a1 = Pt[k * 65 + ty * 4 + 1];
            float a2 = Pt[k * 65 + ty * 4 + 2];
            float a3 = Pt[k * 65 + ty * 4 + 3];
            float b0 = Vs[k * 64 + tx * 4 + 0];
            float b1 = Vs[k * 64 + tx * 4 + 1];
            float b2 = Vs[k * 64 + tx * 4 + 2];
            float b3 = Vs[k * 64 + tx * 4 + 3];
            o[0][0] = fmaf(a0, b0, o[0][0]); o[0][1] = fmaf(a0, b1, o[0][1]);
            o[0][2] = fmaf(a0, b2, o[0][2]); o[0][3] = fmaf(a0, b3, o[0][3]);
            o[1][0] = fmaf(a1, b0, o[1][0]); o[1][1] = fmaf(a1, b1, o[1][1]);
            o[1][2] = fmaf(a1, b2, o[1][2]); o[1][3] = fmaf(a1, b3, o[1][3]);
            o[2][0] = fmaf(a2, b0, o[2][0]); o[2][1] = fmaf(a2, b1, o[2][1]);
            o[2][2] = fmaf(a2, b2, o[2][2]); o[2][3] = fmaf(a2, b3, o[2][3]);
            o[3][0] = fmaf(a3, b0, o[3][0]); o[3][1] = fmaf(a3, b1, o[3][1]);
            o[3][2] = fmaf(a3, b2, o[3][2]); o[3][3] = fmaf(a3, b3, o[3][3]);
        }
    }

    float* yb = Y + ((size_t)b * Tn + q0) * Dm + h * 64;
#pragma unroll
    for (int i = 0; i < 4; i++) {
        float inv = 1.0f / l[i];
#pragma unroll
        for (int j = 0; j < 4; j++)
            yb[(size_t)(ty * 4 + i) * Dm + tx * 4 + j] = o[i][j] * inv;
    }
}

// ---------------- launch ----------------
extern "C" void kernel_launch(void* const* d_in, const int* in_sizes, int n_in,
                              void* d_out, int out_size)
{
    (void)in_sizes; (void)n_in; (void)out_size;
    const float* x     = (const float*)d_in[0];
    const float* Wqkv  = (const float*)d_in[1];
    const float* Wproj = (const float*)d_in[2];
    const float* Wfc1  = (const float*)d_in[3];
    const float* Wfc2  = (const float*)d_in[4];
    const float* ln1g  = (const float*)d_in[5];
    const float* ln1b  = (const float*)d_in[6];
    const float* ln2g  = (const float*)d_in[7];
    const float* ln2b  = (const float*)d_in[8];
    float* out = (float*)d_out;

    float *h, *qkv, *y, *x1, *a;
    cudaGetSymbolAddress((void**)&h,   g_h);
    cudaGetSymbolAddress((void**)&qkv, g_qkv);
    cudaGetSymbolAddress((void**)&y,   g_y);
    cudaGetSymbolAddress((void**)&x1,  g_x1);
    cudaGetSymbolAddress((void**)&a,   g_a);

    const int attn_smem = ATTN_SMEM_FLOATS * (int)sizeof(float);
    cudaFuncSetAttribute(attn_kernel, cudaFuncAttributeMaxDynamicSharedMemorySize, attn_smem);

    // 1) ln1
    ln_kernel<<<Mrows, 256>>>(x, ln1g, ln1b, h);
    // 2) qkv = h @ W_qkv   [4096 x 3072], K=1024
    mma_gemm<0, 0><<<dim3(3 * Dm / 128, Mrows / 128), 128>>>(h, Wqkv, nullptr, qkv, Mrows, 3 * Dm, Dm);
    // 3) attention
    attn_kernel<<<dim3(Tn / 64, Hn, Bn), 256, attn_smem>>>(qkv, y);
    // 4) x1 = x + y @ W_proj   [4096 x 1024], K=1024
    mma_gemm<0, 1><<<dim3(Dm / 128, Mrows / 128), 128>>>(y, Wproj, x, x1, Mrows, Dm, Dm);
    // 5) ln2
    ln_kernel<<<Mrows, 256>>>(x1, ln2g, ln2b, h);
    // 6) a = gelu(h @ W_fc1)   [4096 x 4096], K=1024
    mma_gemm<1, 0><<<dim3(DFFn / 128, Mrows / 128), 128>>>(h, Wfc1, nullptr, a, Mrows, DFFn, Dm);
    // 7) out = x1 + a @ W_fc2  [4096 x 1024], K=4096
    mma_gemm<0, 1><<<dim3(Dm / 128, Mrows / 128), 128>>>(a, Wfc2, x1, out, Mrows, Dm, DFFn);
}

// round 5
// speedup vs baseline: 2.5932x; 1.4803x over previous
#include <cuda_runtime.h>
#include <math.h>
#include <stdint.h>

// ---------------- problem constants ----------------
#define Dm   1024
#define Tn   2048
#define Bn   2
#define Hn   16
#define DFFn 4096
#define Mrows (Bn * Tn)   // 4096

// ---------------- scratch (no allocation allowed) ----------------
__device__ float g_h  [(size_t)Mrows * Dm];
__device__ float g_qkv[(size_t)Mrows * 3 * Dm];
__device__ float g_y  [(size_t)Mrows * Dm];
__device__ float g_x1 [(size_t)Mrows * Dm];
__device__ float g_a  [(size_t)Mrows * DFFn];

// ---------------- helpers ----------------
__device__ __forceinline__ float to_tf32(float x) {
    uint32_t u;
    asm("cvt.rna.tf32.f32 %0, %1;" : "=r"(u) : "f"(x));
    return __uint_as_float(u);
}
__device__ __forceinline__ uint32_t f2u(float x) { return __float_as_uint(x); }

__device__ __forceinline__ void mma_tf32(float* c,
                                         uint32_t a0, uint32_t a1, uint32_t a2, uint32_t a3,
                                         uint32_t b0, uint32_t b1) {
    asm volatile(
        "mma.sync.aligned.m16n8k8.row.col.f32.tf32.tf32.f32 "
        "{%0,%1,%2,%3}, {%4,%5,%6,%7}, {%8,%9}, {%0,%1,%2,%3};"
        : "+f"(c[0]), "+f"(c[1]), "+f"(c[2]), "+f"(c[3])
        : "r"(a0), "r"(a1), "r"(a2), "r"(a3), "r"(b0), "r"(b1));
}

__device__ __forceinline__ float gelu_exact(float x) {
    return 0.5f * x * (1.0f + erff(x * 0.70710678118654752f));
}

// ---------------- LayerNorm ----------------
__global__ void ln_kernel(const float* __restrict__ X,
                          const float* __restrict__ gw,
                          const float* __restrict__ bw,
                          float* __restrict__ O)
{
    int row = blockIdx.x;
    int tid = threadIdx.x;
    const float4* xr = (const float4*)(X + (size_t)row * Dm);
    float4 v = xr[tid];
    float s  = v.x + v.y + v.z + v.w;
    float sq = v.x * v.x + v.y * v.y + v.z * v.z + v.w * v.w;
#pragma unroll
    for (int o = 16; o > 0; o >>= 1) {
        s  += __shfl_xor_sync(0xffffffffu, s,  o);
        sq += __shfl_xor_sync(0xffffffffu, sq, o);
    }
    __shared__ float ws[8], wq[8];
    int wid = tid >> 5, lane = tid & 31;
    if (lane == 0) { ws[wid] = s; wq[wid] = sq; }
    __syncthreads();
    float ts = 0.f, tq = 0.f;
#pragma unroll
    for (int i = 0; i < 8; i++) { ts += ws[i]; tq += wq[i]; }
    float mean = ts * (1.0f / Dm);
    float var  = tq * (1.0f / Dm) - mean * mean;
    float rstd = rsqrtf(var + 1e-5f);
    float4 g4 = ((const float4*)gw)[tid];
    float4 b4 = ((const float4*)bw)[tid];
    float4 o4;
    o4.x = (v.x - mean) * rstd * g4.x + b4.x;
    o4.y = (v.y - mean) * rstd * g4.y + b4.y;
    o4.z = (v.z - mean) * rstd * g4.z + b4.z;
    o4.w = (v.w - mean) * rstd * g4.w + b4.w;
    ((float4*)(O + (size_t)row * Dm))[tid] = o4;
}

// ---------------- TF32 tensor-core GEMM ----------------
// Block tile 128x128, BK=16, 8 warps (2 along M x 4 along N), warp tile 64x32.
template <int GELU, int RESID>
__global__ __launch_bounds__(256, 2)
void mma_gemm(const float* __restrict__ A, const float* __restrict__ B,
              const float* __restrict__ R, float* __restrict__ C,
              int M, int N, int K)
{
    __shared__ float As[128][20];   // [m][k]
    __shared__ float Bs[16][136];   // [k][n]

    const int tid  = threadIdx.x;
    const int lane = tid & 31;
    const int warp = tid >> 5;      // 0..7
    const int wm = warp & 1;        // 2 warps along M (64 rows each)
    const int wn = warp >> 1;       // 4 warps along N (32 cols each)
    const int g  = lane >> 2;
    const int qk = lane & 3;
    const int bx = blockIdx.x, by = blockIdx.y;

    const int arow = tid >> 1;           // 0..127
    const int acol = (tid & 1) * 8;      // 0 or 8
    const int brow = tid >> 5;           // 0..7 (also +8)
    const int bcol = (tid & 31) * 4;

    const float* Ag = A + (size_t)(by * 128 + arow) * K + acol;
    const float* Bg = B + (size_t)brow * N + bx * 128 + bcol;

    float acc[4][4][4];
#pragma unroll
    for (int mf = 0; mf < 4; mf++)
#pragma unroll
        for (int nf = 0; nf < 4; nf++)
#pragma unroll
            for (int r = 0; r < 4; r++) acc[mf][nf][r] = 0.f;

    float4 pa0 = *(const float4*)(Ag);
    float4 pa1 = *(const float4*)(Ag + 4);
    float4 pb0 = *(const float4*)(Bg);
    float4 pb1 = *(const float4*)(Bg + (size_t)8 * N);

    const int nIter = K / 16;
    for (int it = 0; it < nIter; it++) {
        float4 v;
        v = pa0;
        v.x = to_tf32(v.x); v.y = to_tf32(v.y); v.z = to_tf32(v.z); v.w = to_tf32(v.w);
        *(float4*)&As[arow][acol] = v;
        v = pa1;
        v.x = to_tf32(v.x); v.y = to_tf32(v.y); v.z = to_tf32(v.z); v.w = to_tf32(v.w);
        *(float4*)&As[arow][acol + 4] = v;
        v = pb0;
        v.x = to_tf32(v.x); v.y = to_tf32(v.y); v.z = to_tf32(v.z); v.w = to_tf32(v.w);
        *(float4*)&Bs[brow][bcol] = v;
        v = pb1;
        v.x = to_tf32(v.x); v.y = to_tf32(v.y); v.z = to_tf32(v.z); v.w = to_tf32(v.w);
        *(float4*)&Bs[brow + 8][bcol] = v;
        __syncthreads();

        if (it + 1 < nIter) {
            int k0 = (it + 1) * 16;
            pa0 = *(const float4*)(Ag + k0);
            pa1 = *(const float4*)(Ag + k0 + 4);
            pb0 = *(const float4*)(Bg + (size_t)k0 * N);
            pb1 = *(const float4*)(Bg + (size_t)(k0 + 8) * N);
        }

#pragma unroll
        for (int ks = 0; ks < 2; ks++) {
            const int kc = ks * 8 + qk;
            uint32_t af[4][4];
#pragma unroll
            for (int mf = 0; mf < 4; mf++) {
                int r0 = wm * 64 + mf * 16 + g;
                af[mf][0] = f2u(As[r0][kc]);
                af[mf][1] = f2u(As[r0 + 8][kc]);
                af[mf][2] = f2u(As[r0][kc + 4]);
                af[mf][3] = f2u(As[r0 + 8][kc + 4]);
            }
            uint32_t bf[4][2];
#pragma unroll
            for (int nf = 0; nf < 4; nf++) {
                int n0 = wn * 32 + nf * 8 + g;
                bf[nf][0] = f2u(Bs[kc][n0]);
                bf[nf][1] = f2u(Bs[kc + 4][n0]);
            }
#pragma unroll
            for (int mf = 0; mf < 4; mf++)
#pragma unroll
                for (int nf = 0; nf < 4; nf++)
                    mma_tf32(acc[mf][nf], af[mf][0], af[mf][1], af[mf][2], af[mf][3],
                             bf[nf][0], bf[nf][1]);
        }
        __syncthreads();
    }

#pragma unroll
    for (int mf = 0; mf < 4; mf++) {
        int r0 = by * 128 + wm * 64 + mf * 16 + g;
#pragma unroll
        for (int nf = 0; nf < 4; nf++) {
            int c0 = bx * 128 + wn * 32 + nf * 8 + qk * 2;
            float2 v0, v1;
            v0.x = acc[mf][nf][0]; v0.y = acc[mf][nf][1];
            v1.x = acc[mf][nf][2]; v1.y = acc[mf][nf][3];
            if (GELU) {
                v0.x = gelu_exact(v0.x); v0.y = gelu_exact(v0.y);
                v1.x = gelu_exact(v1.x); v1.y = gelu_exact(v1.y);
            }
            if (RESID) {
                float2 r0v = *(const float2*)(R + (size_t)r0 * N + c0);
                float2 r1v = *(const float2*)(R + (size_t)(r0 + 8) * N + c0);
                v0.x += r0v.x; v0.y += r0v.y;
                v1.x += r1v.x; v1.y += r1v.y;
            }
            *(float2*)(C + (size_t)r0 * N + c0)       = v0;
            *(float2*)(C + (size_t)(r0 + 8) * N + c0) = v1;
        }
    }
}

// ---------------- Flash attention with TF32 tensor cores ----------------
// BQ=64, BK=64, hd=64. 4 warps: warp w owns q rows [w*16, w*16+16).
// smem: Qs[64][68], Ks[64][68], Ps[64][68] (warp-private rows), Vs[64][72]
#define QS_STRIDE 68
#define VS_STRIDE 72
#define ATTN_SMEM_BYTES ((3 * 64 * QS_STRIDE + 64 * VS_STRIDE) * 4)

__global__ __launch_bounds__(128, 3)
void attn_mma(const float* __restrict__ QKV, float* __restrict__ Y)
{
    extern __shared__ float sm[];
    float* Qs = sm;                        // [64][68]
    float* Ks = Qs + 64 * QS_STRIDE;       // [64][68]
    float* Ps = Ks + 64 * QS_STRIDE;       // [64][68]
    float* Vs = Ps + 64 * QS_STRIDE;       // [64][72]

    const int tid  = threadIdx.x;
    const int lane = tid & 31;
    const int warp = tid >> 5;             // 0..3
    const int g  = lane >> 2;
    const int qk = lane & 3;

    const int qt = gridDim.x - 1 - blockIdx.x;   // heavy blocks first
    const int h  = blockIdx.y;
    const int b  = blockIdx.z;
    const int q0 = qt * 64;
    const int C3 = 3 * Dm;
    const float* base = QKV + (size_t)b * Tn * C3;

    // load Q tile, pre-scaled by 1/sqrt(64), tf32-rounded
    for (int i = tid; i < 64 * 16; i += 128) {
        int r = i >> 4, c = (i & 15) * 4;
        float4 v = *(const float4*)(base + (size_t)(q0 + r) * C3 + h * 64 + c);
        Qs[r * QS_STRIDE + c + 0] = to_tf32(v.x * 0.125f);
        Qs[r * QS_STRIDE + c + 1] = to_tf32(v.y * 0.125f);
        Qs[r * QS_STRIDE + c + 2] = to_tf32(v.z * 0.125f);
        Qs[r * QS_STRIDE + c + 3] = to_tf32(v.w * 0.125f);
    }

    float O[8][4];
#pragma unroll
    for (int nf = 0; nf < 8; nf++)
#pragma unroll
        for (int r = 0; r < 4; r++) O[nf][r] = 0.f;
    float m0 = -1e30f, m1 = -1e30f, l0 = 0.f, l1 = 0.f;

    for (int kt = 0; kt <= qt; kt++) {
        int k0 = kt * 64;
        __syncthreads();   // everyone done with previous Ks/Vs
        for (int i = tid; i < 64 * 16; i += 128) {
            int r = i >> 4, c = (i & 15) * 4;
            const float* kp = base + (size_t)(k0 + r) * C3 + 1024 + h * 64 + c;
            float4 kv = *(const float4*)kp;
            Ks[r * QS_STRIDE + c + 0] = to_tf32(kv.x);
            Ks[r * QS_STRIDE + c + 1] = to_tf32(kv.y);
            Ks[r * QS_STRIDE + c + 2] = to_tf32(kv.z);
            Ks[r * QS_STRIDE + c + 3] = to_tf32(kv.w);
            float4 vv = *(const float4*)(kp + 1024);
            Vs[r * VS_STRIDE + c + 0] = to_tf32(vv.x);
            Vs[r * VS_STRIDE + c + 1] = to_tf32(vv.y);
            Vs[r * VS_STRIDE + c + 2] = to_tf32(vv.z);
            Vs[r * VS_STRIDE + c + 3] = to_tf32(vv.w);
        }
        __syncthreads();

        // ---- S = Q @ K^T  (warp: 16 x 64) ----
        float S[8][4];
#pragma unroll
        for (int nf = 0; nf < 8; nf++)
#pragma unroll
            for (int r = 0; r < 4; r++) S[nf][r] = 0.f;

#pragma unroll
        for (int ks = 0; ks < 8; ks++) {
            const int kc = ks * 8 + qk;
            const int r0 = warp * 16 + g;
            uint32_t a0 = f2u(Qs[r0 * QS_STRIDE + kc]);
            uint32_t a1 = f2u(Qs[(r0 + 8) * QS_STRIDE + kc]);
            uint32_t a2 = f2u(Qs[r0 * QS_STRIDE + kc + 4]);
            uint32_t a3 = f2u(Qs[(r0 + 8) * QS_STRIDE + kc + 4]);
#pragma unroll
            for (int nf = 0; nf < 8; nf++) {
                int n0 = nf * 8 + g;
                uint32_t b0 = f2u(Ks[n0 * QS_STRIDE + kc]);
                uint32_t b1 = f2u(Ks[n0 * QS_STRIDE + kc + 4]);
                mma_tf32(S[nf], a0, a1, a2, a3, b0, b1);
            }
        }

        // ---- causal mask on diagonal tile ----
        if (kt == qt) {
            const int r0 = warp * 16 + g, r1 = r0 + 8;
#pragma unroll
            for (int nf = 0; nf < 8; nf++) {
                int c = nf * 8 + qk * 2;
                if (c     > r0) S[nf][0] = -1e30f;
                if (c + 1 > r0) S[nf][1] = -1e30f;
                if (c     > r1) S[nf][2] = -1e30f;
                if (c + 1 > r1) S[nf][3] = -1e30f;
            }
        }

        // ---- online softmax (rows g and g+8; reduce over quad lanes) ----
        {
            float rm = -1e30f;
#pragma unroll
            for (int nf = 0; nf < 8; nf++) rm = fmaxf(rm, fmaxf(S[nf][0], S[nf][1]));
            rm = fmaxf(rm, __shfl_xor_sync(0xffffffffu, rm, 1));
            rm = fmaxf(rm, __shfl_xor_sync(0xffffffffu, rm, 2));
            float mn = fmaxf(m0, rm);
            float alpha = __expf(m0 - mn);
            m0 = mn;
            float rs = 0.f;
#pragma unroll
            for (int nf = 0; nf < 8; nf++) {
                S[nf][0] = __expf(S[nf][0] - mn);
                S[nf][1] = __expf(S[nf][1] - mn);
                rs += S[nf][0] + S[nf][1];
            }
            rs += __shfl_xor_sync(0xffffffffu, rs, 1);
            rs += __shfl_xor_sync(0xffffffffu, rs, 2);
            l0 = l0 * alpha + rs;
#pragma unroll
            for (int nf = 0; nf < 8; nf++) { O[nf][0] *= alpha; O[nf][1] *= alpha; }
        }
        {
            float rm = -1e30f;
#pragma unroll
            for (int nf = 0; nf < 8; nf++) rm = fmaxf(rm, fmaxf(S[nf][2], S[nf][3]));
            rm = fmaxf(rm, __shfl_xor_sync(0xffffffffu, rm, 1));
            rm = fmaxf(rm, __shfl_xor_sync(0xffffffffu, rm, 2));
            float mn = fmaxf(m1, rm);
            float alpha = __expf(m1 - mn);
            m1 = mn;
            float rs = 0.f;
#pragma unroll
            for (int nf = 0; nf < 8; nf++) {
                S[nf][2] = __expf(S[nf][2] - mn);
                S[nf][3] = __expf(S[nf][3] - mn);
                rs += S[nf][2] + S[nf][3];
            }
            rs += __shfl_xor_sync(0xffffffffu, rs, 1);
            rs += __shfl_xor_sync(0xffffffffu, rs, 2);
            l1 = l1 * alpha + rs;
#pragma unroll
            for (int nf = 0; nf < 8; nf++) { O[nf][2] *= alpha; O[nf][3] *= alpha; }
        }

        // ---- write P (tf32) to warp-private Ps rows ----
        {
            const int r0 = warp * 16 + g;
#pragma unroll
            for (int nf = 0; nf < 8; nf++) {
                int c = nf * 8 + qk * 2;
                float2 p0; p0.x = to_tf32(S[nf][0]); p0.y = to_tf32(S[nf][1]);
                float2 p1; p1.x = to_tf32(S[nf][2]); p1.y = to_tf32(S[nf][3]);
                *(float2*)&Ps[r0 * QS_STRIDE + c]       = p0;
                *(float2*)&Ps[(r0 + 8) * QS_STRIDE + c] = p1;
            }
        }
        __syncwarp();

        // ---- O += P @ V  (k = key dim) ----
#pragma unroll
        for (int ks = 0; ks < 8; ks++) {
            const int kc = ks * 8 + qk;
            const int r0 = warp * 16 + g;
            uint32_t a0 = f2u(Ps[r0 * QS_STRIDE + kc]);
            uint32_t a1 = f2u(Ps[(r0 + 8) * QS_STRIDE + kc]);
            uint32_t a2 = f2u(Ps[r0 * QS_STRIDE + kc + 4]);
            uint32_t a3 = f2u(Ps[(r0 + 8) * QS_STRIDE + kc + 4]);
#pragma unroll
            for (int nf = 0; nf < 8; nf++) {
                int n0 = nf * 8 + g;
                uint32_t b0 = f2u(Vs[kc * VS_STRIDE + n0]);
                uint32_t b1 = f2u(Vs[(kc + 4) * VS_STRIDE + n0]);
                mma_tf32(O[nf], a0, a1, a2, a3, b0, b1);
            }
        }
    }

    // ---- epilogue: divide by l, write Y ----
    const float inv0 = 1.0f / l0, inv1 = 1.0f / l1;
    const int qr = q0 + warp * 16 + g;
    float* y0 = Y + ((size_t)b * Tn + qr) * Dm + h * 64;
    float* y1 = y0 + (size_t)8 * Dm;
#pragma unroll
    for (int nf = 0; nf < 8; nf++) {
        int c = nf * 8 + qk * 2;
        float2 v0; v0.x = O[nf][0] * inv0; v0.y = O[nf][1] * inv0;
        float2 v1; v1.x = O[nf][2] * inv1; v1.y = O[nf][3] * inv1;
        *(float2*)(y0 + c) = v0;
        *(float2*)(y1 + c) = v1;
    }
}

// ---------------- launch ----------------
extern "C" void kernel_launch(void* const* d_in, const int* in_sizes, int n_in,
                              void* d_out, int out_size)
{
    (void)in_sizes; (void)n_in; (void)out_size;
    const float* x     = (const float*)d_in[0];
    const float* Wqkv  = (const float*)d_in[1];
    const float* Wproj = (const float*)d_in[2];
    const float* Wfc1  = (const float*)d_in[3];
    const float* Wfc2  = (const float*)d_in[4];
    const float* ln1g  = (const float*)d_in[5];
    const float* ln1b  = (const float*)d_in[6];
    const float* ln2g  = (const float*)d_in[7];
    const float* ln2b  = (const float*)d_in[8];
    float* out = (float*)d_out;

    float *h, *qkv, *y, *x1, *a;
    cudaGetSymbolAddress((void**)&h,   g_h);
    cudaGetSymbolAddress((void**)&qkv, g_qkv);
    cudaGetSymbolAddress((void**)&y,   g_y);
    cudaGetSymbolAddress((void**)&x1,  g_x1);
    cudaGetSymbolAddress((void**)&a,   g_a);

    cudaFuncSetAttribute(attn_mma, cudaFuncAttributeMaxDynamicSharedMemorySize, ATTN_SMEM_BYTES);

    // 1) ln1
    ln_kernel<<<Mrows, 256>>>(x, ln1g, ln1b, h);
    // 2) qkv = h @ W_qkv   [4096 x 3072], K=1024
    mma_gemm<0, 0><<<dim3(3 * Dm / 128, Mrows / 128), 256>>>(h, Wqkv, nullptr, qkv, Mrows, 3 * Dm, Dm);
    // 3) attention (tf32 tensor cores)
    attn_mma<<<dim3(Tn / 64, Hn, Bn), 128, ATTN_SMEM_BYTES>>>(qkv, y);
    // 4) x1 = x + y @ W_proj   [4096 x 1024], K=1024
    mma_gemm<0, 1><<<dim3(Dm / 128, Mrows / 128), 256>>>(y, Wproj, x, x1, Mrows, Dm, Dm);
    // 5) ln2
    ln_kernel<<<Mrows, 256>>>(x1, ln2g, ln2b, h);
    // 6) a = gelu(h @ W_fc1)   [4096 x 4096], K=1024
    mma_gemm<1, 0><<<dim3(DFFn / 128, Mrows / 128), 256>>>(h, Wfc1, nullptr, a, Mrows, DFFn, Dm);
    // 7) out = x1 + a @ W_fc2  [4096 x 1024], K=4096
    mma_gemm<0, 1><<<dim3(Dm / 128, Mrows / 128), 256>>>(a, Wfc2, x1, out, Mrows, Dm, DFFn);
}

// round 6
// speedup vs baseline: 2.6045x; 1.0043x over previous
#include <cuda_runtime.h>
#include <math.h>
#include <stdint.h>

// ---------------- problem constants ----------------
#define Dm   1024
#define Tn   2048
#define Bn   2
#define Hn   16
#define DFFn 4096
#define Mrows (Bn * Tn)   // 4096

// ---------------- scratch (no allocation allowed) ----------------
__device__ float g_h  [(size_t)Mrows * Dm];
__device__ float g_qkv[(size_t)Mrows * 3 * Dm];
__device__ float g_y  [(size_t)Mrows * Dm];
__device__ float g_x1 [(size_t)Mrows * Dm];
__device__ float g_a  [(size_t)Mrows * DFFn];
// converted (tf32-rounded) weights, packed: qkv | proj | fc1 | fc2
#define WQKV_OFF  0
#define WPROJ_OFF ((size_t)Dm * 3 * Dm)
#define WFC1_OFF  (WPROJ_OFF + (size_t)Dm * Dm)
#define WFC2_OFF  (WFC1_OFF + (size_t)Dm * DFFn)
#define W_TOTAL   (WFC2_OFF + (size_t)DFFn * Dm)
__device__ float g_w[W_TOTAL];

// ---------------- helpers ----------------
__device__ __forceinline__ float to_tf32(float x) {
    uint32_t u;
    asm("cvt.rna.tf32.f32 %0, %1;" : "=r"(u) : "f"(x));
    return __uint_as_float(u);
}
__device__ __forceinline__ uint32_t f2u(float x) { return __float_as_uint(x); }

__device__ __forceinline__ void mma_tf32(float* c,
                                         uint32_t a0, uint32_t a1, uint32_t a2, uint32_t a3,
                                         uint32_t b0, uint32_t b1) {
    asm volatile(
        "mma.sync.aligned.m16n8k8.row.col.f32.tf32.tf32.f32 "
        "{%0,%1,%2,%3}, {%4,%5,%6,%7}, {%8,%9}, {%0,%1,%2,%3};"
        : "+f"(c[0]), "+f"(c[1]), "+f"(c[2]), "+f"(c[3])
        : "r"(a0), "r"(a1), "r"(a2), "r"(a3), "r"(b0), "r"(b1));
}

__device__ __forceinline__ void cp16(uint32_t smem_addr, const void* gptr) {
    asm volatile("cp.async.ca.shared.global [%0], [%1], 16;"
                 :: "r"(smem_addr), "l"(gptr));
}
#define CP_COMMIT() asm volatile("cp.async.commit_group;")
#define CP_WAIT1()  asm volatile("cp.async.wait_group 1;")

__device__ __forceinline__ float gelu_exact(float x) {
    return 0.5f * x * (1.0f + erff(x * 0.70710678118654752f));
}

// ---------------- weight tf32 conversion ----------------
__global__ void cvt_kernel(const float* __restrict__ src, float* __restrict__ dst, int n4)
{
    int i = blockIdx.x * blockDim.x + threadIdx.x;
    int stride = gridDim.x * blockDim.x;
    const float4* s4 = (const float4*)src;
    float4* d4 = (float4*)dst;
    for (int j = i; j < n4; j += stride) {
        float4 v = s4[j];
        v.x = to_tf32(v.x); v.y = to_tf32(v.y);
        v.z = to_tf32(v.z); v.w = to_tf32(v.w);
        d4[j] = v;
    }
}

// ---------------- LayerNorm (tf32-rounded output) ----------------
__global__ void ln_kernel(const float* __restrict__ X,
                          const float* __restrict__ gw,
                          const float* __restrict__ bw,
                          float* __restrict__ O)
{
    int row = blockIdx.x;
    int tid = threadIdx.x;
    const float4* xr = (const float4*)(X + (size_t)row * Dm);
    float4 v = xr[tid];
    float s  = v.x + v.y + v.z + v.w;
    float sq = v.x * v.x + v.y * v.y + v.z * v.z + v.w * v.w;
#pragma unroll
    for (int o = 16; o > 0; o >>= 1) {
        s  += __shfl_xor_sync(0xffffffffu, s,  o);
        sq += __shfl_xor_sync(0xffffffffu, sq, o);
    }
    __shared__ float ws[8], wq[8];
    int wid = tid >> 5, lane = tid & 31;
    if (lane == 0) { ws[wid] = s; wq[wid] = sq; }
    __syncthreads();
    float ts = 0.f, tq = 0.f;
#pragma unroll
    for (int i = 0; i < 8; i++) { ts += ws[i]; tq += wq[i]; }
    float mean = ts * (1.0f / Dm);
    float var  = tq * (1.0f / Dm) - mean * mean;
    float rstd = rsqrtf(var + 1e-5f);
    float4 g4 = ((const float4*)gw)[tid];
    float4 b4 = ((const float4*)bw)[tid];
    float4 o4;
    o4.x = to_tf32((v.x - mean) * rstd * g4.x + b4.x);
    o4.y = to_tf32((v.y - mean) * rstd * g4.y + b4.y);
    o4.z = to_tf32((v.z - mean) * rstd * g4.z + b4.z);
    o4.w = to_tf32((v.w - mean) * rstd * g4.w + b4.w);
    ((float4*)(O + (size_t)row * Dm))[tid] = o4;
}

// ---------------- TF32 GEMM, cp.async 3-stage pipeline ----------------
// Block 128x128, BK=16, 256 threads, 8 warps (2M x 4N), warp tile 64x32.
// Inputs must already be tf32-rounded bit patterns.
#define STAGES 3
#define AS_STRIDE 20
#define BS_STRIDE 136
#define AS_FLOATS (128 * AS_STRIDE)
#define BS_FLOATS (16 * BS_STRIDE)
#define GEMM_SMEM_BYTES (STAGES * (AS_FLOATS + BS_FLOATS) * 4)

template <int GELU, int RESID, int ROUND>
__global__ __launch_bounds__(256, 2)
void mma_gemm(const float* __restrict__ A, const float* __restrict__ B,
              const float* __restrict__ R, float* __restrict__ C,
              int M, int N, int K)
{
    extern __shared__ float smf[];
    float* AsBase = smf;
    float* BsBase = smf + STAGES * AS_FLOATS;

    const int tid  = threadIdx.x;
    const int lane = tid & 31;
    const int warp = tid >> 5;
    const int wm = warp & 1;
    const int wn = warp >> 1;
    const int g  = lane >> 2;
    const int qk = lane & 3;
    const int bx = blockIdx.x, by = blockIdx.y;

    // async-load mapping
    const int arow = tid >> 1;          // 0..127
    const int acol = (tid & 1) * 8;     // 0 or 8
    const int brow = tid >> 4;          // 0..15
    const int bcol = (tid & 15) * 8;    // 0..120

    const float* Ag = A + (size_t)(by * 128 + arow) * K + acol;
    const float* Bg = B + (size_t)brow * N + bx * 128 + bcol;

    const uint32_t saA = (uint32_t)__cvta_generic_to_shared(AsBase)
                       + (uint32_t)((arow * AS_STRIDE + acol) * 4);
    const uint32_t saB = (uint32_t)__cvta_generic_to_shared(BsBase)
                       + (uint32_t)((brow * BS_STRIDE + bcol) * 4);

    float acc[4][4][4];
#pragma unroll
    for (int mf = 0; mf < 4; mf++)
#pragma unroll
        for (int nf = 0; nf < 4; nf++)
#pragma unroll
            for (int r = 0; r < 4; r++) acc[mf][nf][r] = 0.f;

    const int nIter = K / 16;

    // prologue: issue STAGES-1 stages
#pragma unroll
    for (int s = 0; s < STAGES - 1; s++) {
        int k0 = s * 16;
        cp16(saA + s * (AS_FLOATS * 4),      Ag + k0);
        cp16(saA + s * (AS_FLOATS * 4) + 16, Ag + k0 + 4);
        cp16(saB + s * (BS_FLOATS * 4),      Bg + (size_t)k0 * N);
        cp16(saB + s * (BS_FLOATS * 4) + 16, Bg + (size_t)k0 * N + 4);
        CP_COMMIT();
    }

    for (int it = 0; it < nIter; it++) {
        CP_WAIT1();            // stage `it` resident
        __syncthreads();

        int nx = it + STAGES - 1;
        if (nx < nIter) {      // fill slot freed at iteration it-1
            int slot = nx % STAGES;
            int k0 = nx * 16;
            cp16(saA + slot * (AS_FLOATS * 4),      Ag + k0);
            cp16(saA + slot * (AS_FLOATS * 4) + 16, Ag + k0 + 4);
            cp16(saB + slot * (BS_FLOATS * 4),      Bg + (size_t)k0 * N);
            cp16(saB + slot * (BS_FLOATS * 4) + 16, Bg + (size_t)k0 * N + 4);
        }
        CP_COMMIT();           // commit (possibly empty) to keep group count uniform

        const float* AsS = AsBase + (it % STAGES) * AS_FLOATS;
        const float* BsS = BsBase + (it % STAGES) * BS_FLOATS;

#pragma unroll
        for (int ks = 0; ks < 2; ks++) {
            const int kc = ks * 8 + qk;
            uint32_t af[4][4];
#pragma unroll
            for (int mf = 0; mf < 4; mf++) {
                int r0 = wm * 64 + mf * 16 + g;
                af[mf][0] = f2u(AsS[r0 * AS_STRIDE + kc]);
                af[mf][1] = f2u(AsS[(r0 + 8) * AS_STRIDE + kc]);
                af[mf][2] = f2u(AsS[r0 * AS_STRIDE + kc + 4]);
                af[mf][3] = f2u(AsS[(r0 + 8) * AS_STRIDE + kc + 4]);
            }
            uint32_t bf[4][2];
#pragma unroll
            for (int nf = 0; nf < 4; nf++) {
                int n0 = wn * 32 + nf * 8 + g;
                bf[nf][0] = f2u(BsS[kc * BS_STRIDE + n0]);
                bf[nf][1] = f2u(BsS[(kc + 4) * BS_STRIDE + n0]);
            }
#pragma unroll
            for (int mf = 0; mf < 4; mf++)
#pragma unroll
                for (int nf = 0; nf < 4; nf++)
                    mma_tf32(acc[mf][nf], af[mf][0], af[mf][1], af[mf][2], af[mf][3],
                             bf[nf][0], bf[nf][1]);
        }
    }

#pragma unroll
    for (int mf = 0; mf < 4; mf++) {
        int r0 = by * 128 + wm * 64 + mf * 16 + g;
#pragma unroll
        for (int nf = 0; nf < 4; nf++) {
            int c0 = bx * 128 + wn * 32 + nf * 8 + qk * 2;
            float2 v0, v1;
            v0.x = acc[mf][nf][0]; v0.y = acc[mf][nf][1];
            v1.x = acc[mf][nf][2]; v1.y = acc[mf][nf][3];
            if (GELU) {
                v0.x = gelu_exact(v0.x); v0.y = gelu_exact(v0.y);
                v1.x = gelu_exact(v1.x); v1.y = gelu_exact(v1.y);
            }
            if (RESID) {
                float2 r0v = *(const float2*)(R + (size_t)r0 * N + c0);
                float2 r1v = *(const float2*)(R + (size_t)(r0 + 8) * N + c0);
                v0.x += r0v.x; v0.y += r0v.y;
                v1.x += r1v.x; v1.y += r1v.y;
            }
            if (ROUND) {
                v0.x = to_tf32(v0.x); v0.y = to_tf32(v0.y);
                v1.x = to_tf32(v1.x); v1.y = to_tf32(v1.y);
            }
            *(float2*)(C + (size_t)r0 * N + c0)       = v0;
            *(float2*)(C + (size_t)(r0 + 8) * N + c0) = v1;
        }
    }
}

// ---------------- Flash attention with TF32 tensor cores ----------------
#define QS_STRIDE 68
#define VS_STRIDE 72
#define ATTN_SMEM_BYTES ((3 * 64 * QS_STRIDE + 64 * VS_STRIDE) * 4)

__global__ __launch_bounds__(128, 3)
void attn_mma(const float* __restrict__ QKV, float* __restrict__ Y)
{
    extern __shared__ float sm[];
    float* Qs = sm;
    float* Ks = Qs + 64 * QS_STRIDE;
    float* Ps = Ks + 64 * QS_STRIDE;
    float* Vs = Ps + 64 * QS_STRIDE;

    const int tid  = threadIdx.x;
    const int lane = tid & 31;
    const int warp = tid >> 5;
    const int g  = lane >> 2;
    const int qk = lane & 3;

    const int qt = gridDim.x - 1 - blockIdx.x;
    const int h  = blockIdx.y;
    const int b  = blockIdx.z;
    const int q0 = qt * 64;
    const int C3 = 3 * Dm;
    const float* base = QKV + (size_t)b * Tn * C3;

    for (int i = tid; i < 64 * 16; i += 128) {
        int r = i >> 4, c = (i & 15) * 4;
        float4 v = *(const float4*)(base + (size_t)(q0 + r) * C3 + h * 64 + c);
        Qs[r * QS_STRIDE + c + 0] = to_tf32(v.x * 0.125f);
        Qs[r * QS_STRIDE + c + 1] = to_tf32(v.y * 0.125f);
        Qs[r * QS_STRIDE + c + 2] = to_tf32(v.z * 0.125f);
        Qs[r * QS_STRIDE + c + 3] = to_tf32(v.w * 0.125f);
    }

    float O[8][4];
#pragma unroll
    for (int nf = 0; nf < 8; nf++)
#pragma unroll
        for (int r = 0; r < 4; r++) O[nf][r] = 0.f;
    float m0 = -1e30f, m1 = -1e30f, l0 = 0.f, l1 = 0.f;

    for (int kt = 0; kt <= qt; kt++) {
        int k0 = kt * 64;
        __syncthreads();
        for (int i = tid; i < 64 * 16; i += 128) {
            int r = i >> 4, c = (i & 15) * 4;
            const float* kp = base + (size_t)(k0 + r) * C3 + 1024 + h * 64 + c;
            float4 kv = *(const float4*)kp;
            Ks[r * QS_STRIDE + c + 0] = to_tf32(kv.x);
            Ks[r * QS_STRIDE + c + 1] = to_tf32(kv.y);
            Ks[r * QS_STRIDE + c + 2] = to_tf32(kv.z);
            Ks[r * QS_STRIDE + c + 3] = to_tf32(kv.w);
            float4 vv = *(const float4*)(kp + 1024);
            Vs[r * VS_STRIDE + c + 0] = to_tf32(vv.x);
            Vs[r * VS_STRIDE + c + 1] = to_tf32(vv.y);
            Vs[r * VS_STRIDE + c + 2] = to_tf32(vv.z);
            Vs[r * VS_STRIDE + c + 3] = to_tf32(vv.w);
        }
        __syncthreads();

        float S[8][4];
#pragma unroll
        for (int nf = 0; nf < 8; nf++)
#pragma unroll
            for (int r = 0; r < 4; r++) S[nf][r] = 0.f;

#pragma unroll
        for (int ks = 0; ks < 8; ks++) {
            const int kc = ks * 8 + qk;
            const int r0 = warp * 16 + g;
            uint32_t a0 = f2u(Qs[r0 * QS_STRIDE + kc]);
            uint32_t a1 = f2u(Qs[(r0 + 8) * QS_STRIDE + kc]);
            uint32_t a2 = f2u(Qs[r0 * QS_STRIDE + kc + 4]);
            uint32_t a3 = f2u(Qs[(r0 + 8) * QS_STRIDE + kc + 4]);
#pragma unroll
            for (int nf = 0; nf < 8; nf++) {
                int n0 = nf * 8 + g;
                uint32_t b0 = f2u(Ks[n0 * QS_STRIDE + kc]);
                uint32_t b1 = f2u(Ks[n0 * QS_STRIDE + kc + 4]);
                mma_tf32(S[nf], a0, a1, a2, a3, b0, b1);
            }
        }

        if (kt == qt) {
            const int r0 = warp * 16 + g, r1 = r0 + 8;
#pragma unroll
            for (int nf = 0; nf < 8; nf++) {
                int c = nf * 8 + qk * 2;
                if (c     > r0) S[nf][0] = -1e30f;
                if (c + 1 > r0) S[nf][1] = -1e30f;
                if (c     > r1) S[nf][2] = -1e30f;
                if (c + 1 > r1) S[nf][3] = -1e30f;
            }
        }

        {
            float rm = -1e30f;
#pragma unroll
            for (int nf = 0; nf < 8; nf++) rm = fmaxf(rm, fmaxf(S[nf][0], S[nf][1]));
            rm = fmaxf(rm, __shfl_xor_sync(0xffffffffu, rm, 1));
            rm = fmaxf(rm, __shfl_xor_sync(0xffffffffu, rm, 2));
            float mn = fmaxf(m0, rm);
            float alpha = __expf(m0 - mn);
            m0 = mn;
            float rs = 0.f;
#pragma unroll
            for (int nf = 0; nf < 8; nf++) {
                S[nf][0] = __expf(S[nf][0] - mn);
                S[nf][1] = __expf(S[nf][1] - mn);
                rs += S[nf][0] + S[nf][1];
            }
            rs += __shfl_xor_sync(0xffffffffu, rs, 1);
            rs += __shfl_xor_sync(0xffffffffu, rs, 2);
            l0 = l0 * alpha + rs;
#pragma unroll
            for (int nf = 0; nf < 8; nf++) { O[nf][0] *= alpha; O[nf][1] *= alpha; }
        }
        {
            float rm = -1e30f;
#pragma unroll
            for (int nf = 0; nf < 8; nf++) rm = fmaxf(rm, fmaxf(S[nf][2], S[nf][3]));
            rm = fmaxf(rm, __shfl_xor_sync(0xffffffffu, rm, 1));
            rm = fmaxf(rm, __shfl_xor_sync(0xffffffffu, rm, 2));
            float mn = fmaxf(m1, rm);
            float alpha = __expf(m1 - mn);
            m1 = mn;
            float rs = 0.f;
#pragma unroll
            for (int nf = 0; nf < 8; nf++) {
                S[nf][2] = __expf(S[nf][2] - mn);
                S[nf][3] = __expf(S[nf][3] - mn);
                rs += S[nf][2] + S[nf][3];
            }
            rs += __shfl_xor_sync(0xffffffffu, rs, 1);
            rs += __shfl_xor_sync(0xffffffffu, rs, 2);
            l1 = l1 * alpha + rs;
#pragma unroll
            for (int nf = 0; nf < 8; nf++) { O[nf][2] *= alpha; O[nf][3] *= alpha; }
        }

        {
            const int r0 = warp * 16 + g;
#pragma unroll
            for (int nf = 0; nf < 8; nf++) {
                int c = nf * 8 + qk * 2;
                float2 p0; p0.x = to_tf32(S[nf][0]); p0.y = to_tf32(S[nf][1]);
                float2 p1; p1.x = to_tf32(S[nf][2]); p1.y = to_tf32(S[nf][3]);
                *(float2*)&Ps[r0 * QS_STRIDE + c]       = p0;
                *(float2*)&Ps[(r0 + 8) * QS_STRIDE + c] = p1;
            }
        }
        __syncwarp();

#pragma unroll
        for (int ks = 0; ks < 8; ks++) {
            const int kc = ks * 8 + qk;
            const int r0 = warp * 16 + g;
            uint32_t a0 = f2u(Ps[r0 * QS_STRIDE + kc]);
            uint32_t a1 = f2u(Ps[(r0 + 8) * QS_STRIDE + kc]);
            uint32_t a2 = f2u(Ps[r0 * QS_STRIDE + kc + 4]);
            uint32_t a3 = f2u(Ps[(r0 + 8) * QS_STRIDE + kc + 4]);
#pragma unroll
            for (int nf = 0; nf < 8; nf++) {
                int n0 = nf * 8 + g;
                uint32_t b0 = f2u(Vs[kc * VS_STRIDE + n0]);
                uint32_t b1 = f2u(Vs[(kc + 4) * VS_STRIDE + n0]);
                mma_tf32(O[nf], a0, a1, a2, a3, b0, b1);
            }
        }
    }

    const float inv0 = 1.0f / l0, inv1 = 1.0f / l1;
    const int qr = q0 + warp * 16 + g;
    float* y0 = Y + ((size_t)b * Tn + qr) * Dm + h * 64;
    float* y1 = y0 + (size_t)8 * Dm;
#pragma unroll
    for (int nf = 0; nf < 8; nf++) {
        int c = nf * 8 + qk * 2;
        float2 v0; v0.x = to_tf32(O[nf][0] * inv0); v0.y = to_tf32(O[nf][1] * inv0);
        float2 v1; v1.x = to_tf32(O[nf][2] * inv1); v1.y = to_tf32(O[nf][3] * inv1);
        *(float2*)(y0 + c) = v0;
        *(float2*)(y1 + c) = v1;
    }
}

// ---------------- launch ----------------
extern "C" void kernel_launch(void* const* d_in, const int* in_sizes, int n_in,
                              void* d_out, int out_size)
{
    (void)in_sizes; (void)n_in; (void)out_size;
    const float* x     = (const float*)d_in[0];
    const float* Wqkv  = (const float*)d_in[1];
    const float* Wproj = (const float*)d_in[2];
    const float* Wfc1  = (const float*)d_in[3];
    const float* Wfc2  = (const float*)d_in[4];
    const float* ln1g  = (const float*)d_in[5];
    const float* ln1b  = (const float*)d_in[6];
    const float* ln2g  = (const float*)d_in[7];
    const float* ln2b  = (const float*)d_in[8];
    float* out = (float*)d_out;

    float *h, *qkv, *y, *x1, *a, *w;
    cudaGetSymbolAddress((void**)&h,   g_h);
    cudaGetSymbolAddress((void**)&qkv, g_qkv);
    cudaGetSymbolAddress((void**)&y,   g_y);
    cudaGetSymbolAddress((void**)&x1,  g_x1);
    cudaGetSymbolAddress((void**)&a,   g_a);
    cudaGetSymbolAddress((void**)&w,   g_w);

    cudaFuncSetAttribute(attn_mma, cudaFuncAttributeMaxDynamicSharedMemorySize, ATTN_SMEM_BYTES);
    cudaFuncSetAttribute(mma_gemm<0,0,0>, cudaFuncAttributeMaxDynamicSharedMemorySize, GEMM_SMEM_BYTES);
    cudaFuncSetAttribute(mma_gemm<0,1,0>, cudaFuncAttributeMaxDynamicSharedMemorySize, GEMM_SMEM_BYTES);
    cudaFuncSetAttribute(mma_gemm<1,0,1>, cudaFuncAttributeMaxDynamicSharedMemorySize, GEMM_SMEM_BYTES);

    // 0) convert weights to tf32 bit patterns (scratch)
    cvt_kernel<<<512, 256>>>(Wqkv,  w + WQKV_OFF,  (int)((size_t)Dm * 3 * Dm / 4));
    cvt_kernel<<<512, 256>>>(Wproj, w + WPROJ_OFF, (int)((size_t)Dm * Dm / 4));
    cvt_kernel<<<512, 256>>>(Wfc1,  w + WFC1_OFF,  (int)((size_t)Dm * DFFn / 4));
    cvt_kernel<<<512, 256>>>(Wfc2,  w + WFC2_OFF,  (int)((size_t)DFFn * Dm / 4));

    // 1) ln1 (tf32-rounded output)
    ln_kernel<<<Mrows, 256>>>(x, ln1g, ln1b, h);
    // 2) qkv = h @ W_qkv
    mma_gemm<0,0,0><<<dim3(3 * Dm / 128, Mrows / 128), 256, GEMM_SMEM_BYTES>>>(
        h, w + WQKV_OFF, nullptr, qkv, Mrows, 3 * Dm, Dm);
    // 3) attention (y tf32-rounded)
    attn_mma<<<dim3(Tn / 64, Hn, Bn), 128, ATTN_SMEM_BYTES>>>(qkv, y);
    // 4) x1 = x + y @ W_proj (full fp32 out)
    mma_gemm<0,1,0><<<dim3(Dm / 128, Mrows / 128), 256, GEMM_SMEM_BYTES>>>(
        y, w + WPROJ_OFF, x, x1, Mrows, Dm, Dm);
    // 5) ln2
    ln_kernel<<<Mrows, 256>>>(x1, ln2g, ln2b, h);
    // 6) a = tf32(gelu(h @ W_fc1))
    mma_gemm<1,0,1><<<dim3(DFFn / 128, Mrows / 128), 256, GEMM_SMEM_BYTES>>>(
        h, w + WFC1_OFF, nullptr, a, Mrows, DFFn, Dm);
    // 7) out = x1 + a @ W_fc2 (full fp32 out)
    mma_gemm<0,1,0><<<dim3(Dm / 128, Mrows / 128), 256, GEMM_SMEM_BYTES>>>(
        a, w + WFC2_OFF, x1, out, Mrows, Dm, DFFn);
}

// round 10
// speedup vs baseline: 3.2478x; 1.2470x over previous
#include <cuda_runtime.h>
#include <math.h>
#include <stdint.h>

// ---------------- problem constants ----------------
#define Dm   1024
#define Tn   2048
#define Bn   2
#define Hn   16
#define DFFn 4096
#define Mrows (Bn * Tn)   // 4096

// ---------------- scratch (no allocation allowed) ----------------
__device__ float g_h  [(size_t)Mrows * Dm];
__device__ float g_qkv[(size_t)Mrows * 3 * Dm];
__device__ float g_y  [(size_t)Mrows * Dm];
__device__ float g_x1 [(size_t)Mrows * Dm];
__device__ float g_a  [(size_t)Mrows * DFFn];
// tf32-rounded weights (plain [K][N] layout): qkv | proj | fc1 | fc2
#define WQKV_OFF  0
#define WPROJ_OFF ((size_t)Dm * 3 * Dm)
#define WFC1_OFF  (WPROJ_OFF + (size_t)Dm * Dm)
#define WFC2_OFF  (WFC1_OFF + (size_t)Dm * DFFn)
#define W_TOTAL   (WFC2_OFF + (size_t)DFFn * Dm)
__device__ float g_w[W_TOTAL];

// ---------------- helpers ----------------
__device__ __forceinline__ float to_tf32(float x) {
    uint32_t u;
    asm("cvt.rna.tf32.f32 %0, %1;" : "=r"(u) : "f"(x));
    return __uint_as_float(u);
}
__device__ __forceinline__ uint32_t f2u(float x) { return __float_as_uint(x); }

__device__ __forceinline__ void mma_tf32(float* c,
                                         uint32_t a0, uint32_t a1, uint32_t a2, uint32_t a3,
                                         uint32_t b0, uint32_t b1) {
    asm volatile(
        "mma.sync.aligned.m16n8k8.row.col.f32.tf32.tf32.f32 "
        "{%0,%1,%2,%3}, {%4,%5,%6,%7}, {%8,%9}, {%0,%1,%2,%3};"
        : "+f"(c[0]), "+f"(c[1]), "+f"(c[2]), "+f"(c[3])
        : "r"(a0), "r"(a1), "r"(a2), "r"(a3), "r"(b0), "r"(b1));
}

__device__ __forceinline__ void cp16(uint32_t smem_addr, const void* gptr) {
    asm volatile("cp.async.cg.shared.global [%0], [%1], 16;"
                 :: "r"(smem_addr), "l"(gptr));
}
#define CP_COMMIT() asm volatile("cp.async.commit_group;")

__device__ __forceinline__ float gelu_exact(float x) {
    return 0.5f * x * (1.0f + erff(x * 0.70710678118654752f));
}

// ---------------- weight tf32 conversion ----------------
__global__ void cvt_kernel(const float* __restrict__ src, float* __restrict__ dst, int n4)
{
    int i = blockIdx.x * blockDim.x + threadIdx.x;
    int stride = gridDim.x * blockDim.x;
    const float4* s4 = (const float4*)src;
    float4* d4 = (float4*)dst;
    for (int j = i; j < n4; j += stride) {
        float4 v = s4[j];
        v.x = to_tf32(v.x); v.y = to_tf32(v.y);
        v.z = to_tf32(v.z); v.w = to_tf32(v.w);
        d4[j] = v;
    }
}

// ---------------- LayerNorm (tf32-rounded output) ----------------
__global__ void ln_kernel(const float* __restrict__ X,
                          const float* __restrict__ gw,
                          const float* __restrict__ bw,
                          float* __restrict__ O)
{
    int row = blockIdx.x;
    int tid = threadIdx.x;
    const float4* xr = (const float4*)(X + (size_t)row * Dm);
    float4 v = xr[tid];
    float s  = v.x + v.y + v.z + v.w;
    float sq = v.x * v.x + v.y * v.y + v.z * v.z + v.w * v.w;
#pragma unroll
    for (int o = 16; o > 0; o >>= 1) {
        s  += __shfl_xor_sync(0xffffffffu, s,  o);
        sq += __shfl_xor_sync(0xffffffffu, sq, o);
    }
    __shared__ float ws[8], wq[8];
    int wid = tid >> 5, lane = tid & 31;
    if (lane == 0) { ws[wid] = s; wq[wid] = sq; }
    __syncthreads();
    float ts = 0.f, tq = 0.f;
#pragma unroll
    for (int i = 0; i < 8; i++) { ts += ws[i]; tq += wq[i]; }
    float mean = ts * (1.0f / Dm);
    float var  = tq * (1.0f / Dm) - mean * mean;
    float rstd = rsqrtf(var + 1e-5f);
    float4 g4 = ((const float4*)gw)[tid];
    float4 b4 = ((const float4*)bw)[tid];
    float4 o4;
    o4.x = to_tf32((v.x - mean) * rstd * g4.x + b4.x);
    o4.y = to_tf32((v.y - mean) * rstd * g4.y + b4.y);
    o4.z = to_tf32((v.z - mean) * rstd * g4.z + b4.z);
    o4.w = to_tf32((v.w - mean) * rstd * g4.w + b4.w);
    ((float4*)(O + (size_t)row * Dm))[tid] = o4;
}

// ---------------- TF32 GEMM, cp.async 4-stage, 4 warps, warp tile 64x64 ----------------
// C = A[MxK] @ B[KxN] (+R) (opt GELU / tf32-round). Inputs pre-rounded tf32.
// Block tile 128x128, BK=16. Warps: 2(M) x 2(N), each 64x64.
#define STAGES 4
#define AS_STRIDE 20
#define BS_STRIDE 136
#define AS_FLOATS (128 * AS_STRIDE)
#define BS_FLOATS (16 * BS_STRIDE)
#define STAGE_FLOATS (AS_FLOATS + BS_FLOATS)
#define GEMM_SMEM_BYTES (STAGES * STAGE_FLOATS * 4)

template <int GELU, int RESID, int ROUND>
__global__ __launch_bounds__(128, 2)
void mma_gemm(const float* __restrict__ A, const float* __restrict__ B,
              const float* __restrict__ R, float* __restrict__ C,
              int M, int N, int K)
{
    extern __shared__ float smf[];

    const int tid  = threadIdx.x;
    const int lane = tid & 31;
    const int warp = tid >> 5;      // 0..3
    const int wm = warp & 1;        // 2 warps along M (64 rows)
    const int wn = warp >> 1;       // 2 warps along N (64 cols)
    const int g  = lane >> 2;
    const int qk = lane & 3;
    const int bx = blockIdx.x, by = blockIdx.y;

    const float* Ag = A + (size_t)(by * 128) * K;
    const float* Bg = B + bx * 128;
    const uint32_t sbase = (uint32_t)__cvta_generic_to_shared(smf);

    float acc[4][8][4];
#pragma unroll
    for (int mf = 0; mf < 4; mf++)
#pragma unroll
        for (int nf = 0; nf < 8; nf++)
#pragma unroll
            for (int r = 0; r < 4; r++) acc[mf][nf][r] = 0.f;

    const int nIter = K / 16;

    // fill stage s with k-chunk ch
    auto fill = [&](int s, int ch) {
        uint32_t sA = sbase + (uint32_t)(s * STAGE_FLOATS * 4);
        uint32_t sB = sA + AS_FLOATS * 4;
        int k0 = ch * 16;
#pragma unroll
        for (int i = 0; i < 4; i++) {                 // A: 128 rows x 16 cols
            int idx = tid + i * 128;
            int r = idx >> 2, c = (idx & 3) * 4;
            cp16(sA + (uint32_t)((r * AS_STRIDE + c) * 4), Ag + (size_t)r * K + k0 + c);
        }
#pragma unroll
        for (int i = 0; i < 4; i++) {                 // B: 16 rows x 128 cols
            int idx = tid + i * 128;
            int r = idx >> 5, c = (idx & 31) * 4;
            cp16(sB + (uint32_t)((r * BS_STRIDE + c) * 4), Bg + (size_t)(k0 + r) * N + c);
        }
    };

    // prologue: STAGES-1 stages in flight
#pragma unroll
    for (int s = 0; s < STAGES - 1; s++) { fill(s, s); CP_COMMIT(); }

    for (int it = 0; it < nIter; it++) {
        asm volatile("cp.async.wait_group %0;" :: "n"(STAGES - 2));
        __syncthreads();

        if (it + STAGES - 1 < nIter) fill((it + STAGES - 1) % STAGES, it + STAGES - 1);
        CP_COMMIT();

        const float* AsS = smf + (it % STAGES) * STAGE_FLOATS;
        const float* BsS = AsS + AS_FLOATS;

#pragma unroll
        for (int ks = 0; ks < 2; ks++) {
            const int kc = ks * 8 + qk;
            uint32_t af[4][4];
#pragma unroll
            for (int mf = 0; mf < 4; mf++) {
                int r0 = wm * 64 + mf * 16 + g;
                af[mf][0] = f2u(AsS[r0 * AS_STRIDE + kc]);
                af[mf][1] = f2u(AsS[(r0 + 8) * AS_STRIDE + kc]);
                af[mf][2] = f2u(AsS[r0 * AS_STRIDE + kc + 4]);
                af[mf][3] = f2u(AsS[(r0 + 8) * AS_STRIDE + kc + 4]);
            }
            uint32_t bf[8][2];
#pragma unroll
            for (int nf = 0; nf < 8; nf++) {
                int n0 = wn * 64 + nf * 8 + g;
                bf[nf][0] = f2u(BsS[kc * BS_STRIDE + n0]);
                bf[nf][1] = f2u(BsS[(kc + 4) * BS_STRIDE + n0]);
            }
#pragma unroll
            for (int mf = 0; mf < 4; mf++)
#pragma unroll
                for (int nf = 0; nf < 8; nf++)
                    mma_tf32(acc[mf][nf], af[mf][0], af[mf][1], af[mf][2], af[mf][3],
                             bf[nf][0], bf[nf][1]);
        }
    }

    // epilogue
#pragma unroll
    for (int mf = 0; mf < 4; mf++) {
        int r0 = by * 128 + wm * 64 + mf * 16 + g;
#pragma unroll
        for (int nf = 0; nf < 8; nf++) {
            int c0 = bx * 128 + wn * 64 + nf * 8 + qk * 2;
            float2 v0, v1;
            v0.x = acc[mf][nf][0]; v0.y = acc[mf][nf][1];
            v1.x = acc[mf][nf][2]; v1.y = acc[mf][nf][3];
            if (GELU) {
                v0.x = gelu_exact(v0.x); v0.y = gelu_exact(v0.y);
                v1.x = gelu_exact(v1.x); v1.y = gelu_exact(v1.y);
            }
            if (RESID) {
                float2 r0v = *(const float2*)(R + (size_t)r0 * N + c0);
                float2 r1v = *(const float2*)(R + (size_t)(r0 + 8) * N + c0);
                v0.x += r0v.x; v0.y += r0v.y;
                v1.x += r1v.x; v1.y += r1v.y;
            }
            if (ROUND) {
                v0.x = to_tf32(v0.x); v0.y = to_tf32(v0.y);
                v1.x = to_tf32(v1.x); v1.y = to_tf32(v1.y);
            }
            *(float2*)(C + (size_t)r0 * N + c0)       = v0;
            *(float2*)(C + (size_t)(r0 + 8) * N + c0) = v1;
        }
    }
}

// ---------------- Flash attention with TF32 tensor cores ----------------
#define QS_STRIDE 68
#define VS_STRIDE 72
#define ATTN_SMEM_BYTES ((3 * 64 * QS_STRIDE + 64 * VS_STRIDE) * 4)

__global__ __launch_bounds__(128, 3)
void attn_mma(const float* __restrict__ QKV, float* __restrict__ Y)
{
    extern __shared__ float sm[];
    float* Qs = sm;
    float* Ks = Qs + 64 * QS_STRIDE;
    float* Ps = Ks + 64 * QS_STRIDE;
    float* Vs = Ps + 64 * QS_STRIDE;

    const int tid  = threadIdx.x;
    const int lane = tid & 31;
    const int warp = tid >> 5;
    const int g  = lane >> 2;
    const int qk = lane & 3;

    const int qt = gridDim.x - 1 - blockIdx.x;
    const int h  = blockIdx.y;
    const int b  = blockIdx.z;
    const int q0 = qt * 64;
    const int C3 = 3 * Dm;
    const float* base = QKV + (size_t)b * Tn * C3;

    for (int i = tid; i < 64 * 16; i += 128) {
        int r = i >> 4, c = (i & 15) * 4;
        float4 v = *(const float4*)(base + (size_t)(q0 + r) * C3 + h * 64 + c);
        Qs[r * QS_STRIDE + c + 0] = to_tf32(v.x * 0.125f);
        Qs[r * QS_STRIDE + c + 1] = to_tf32(v.y * 0.125f);
        Qs[r * QS_STRIDE + c + 2] = to_tf32(v.z * 0.125f);
        Qs[r * QS_STRIDE + c + 3] = to_tf32(v.w * 0.125f);
    }

    float O[8][4];
#pragma unroll
    for (int nf = 0; nf < 8; nf++)
#pragma unroll
        for (int r = 0; r < 4; r++) O[nf][r] = 0.f;
    float m0 = -1e30f, m1 = -1e30f, l0 = 0.f, l1 = 0.f;

    for (int kt = 0; kt <= qt; kt++) {
        int k0 = kt * 64;
        __syncthreads();
        for (int i = tid; i < 64 * 16; i += 128) {
            int r = i >> 4, c = (i & 15) * 4;
            const float* kp = base + (size_t)(k0 + r) * C3 + 1024 + h * 64 + c;
            float4 kv = *(const float4*)kp;
            Ks[r * QS_STRIDE + c + 0] = to_tf32(kv.x);
            Ks[r * QS_STRIDE + c + 1] = to_tf32(kv.y);
            Ks[r * QS_STRIDE + c + 2] = to_tf32(kv.z);
            Ks[r * QS_STRIDE + c + 3] = to_tf32(kv.w);
            float4 vv = *(const float4*)(kp + 1024);
            Vs[r * VS_STRIDE + c + 0] = to_tf32(vv.x);
            Vs[r * VS_STRIDE + c + 1] = to_tf32(vv.y);
            Vs[r * VS_STRIDE + c + 2] = to_tf32(vv.z);
            Vs[r * VS_STRIDE + c + 3] = to_tf32(vv.w);
        }
        __syncthreads();

        float S[8][4];
#pragma unroll
        for (int nf = 0; nf < 8; nf++)
#pragma unroll
            for (int r = 0; r < 4; r++) S[nf][r] = 0.f;

#pragma unroll
        for (int ks = 0; ks < 8; ks++) {
            const int kc = ks * 8 + qk;
            const int r0 = warp * 16 + g;
            uint32_t a0 = f2u(Qs[r0 * QS_STRIDE + kc]);
            uint32_t a1 = f2u(Qs[(r0 + 8) * QS_STRIDE + kc]);
            uint32_t a2 = f2u(Qs[r0 * QS_STRIDE + kc + 4]);
            uint32_t a3 = f2u(Qs[(r0 + 8) * QS_STRIDE + kc + 4]);
#pragma unroll
            for (int nf = 0; nf < 8; nf++) {
                int n0 = nf * 8 + g;
                uint32_t b0 = f2u(Ks[n0 * QS_STRIDE + kc]);
                uint32_t b1 = f2u(Ks[n0 * QS_STRIDE + kc + 4]);
                mma_tf32(S[nf], a0, a1, a2, a3, b0, b1);
            }
        }

        if (kt == qt) {
            const int r0 = warp * 16 + g, r1 = r0 + 8;
#pragma unroll
            for (int nf = 0; nf < 8; nf++) {
                int c = nf * 8 + qk * 2;
                if (c     > r0) S[nf][0] = -1e30f;
                if (c + 1 > r0) S[nf][1] = -1e30f;
                if (c     > r1) S[nf][2] = -1e30f;
                if (c + 1 > r1) S[nf][3] = -1e30f;
            }
        }

        {
            float rm = -1e30f;
#pragma unroll
            for (int nf = 0; nf < 8; nf++) rm = fmaxf(rm, fmaxf(S[nf][0], S[nf][1]));
            rm = fmaxf(rm, __shfl_xor_sync(0xffffffffu, rm, 1));
            rm = fmaxf(rm, __shfl_xor_sync(0xffffffffu, rm, 2));
            float mn = fmaxf(m0, rm);
            float alpha = __expf(m0 - mn);
            m0 = mn;
            float rs = 0.f;
#pragma unroll
            for (int nf = 0; nf < 8; nf++) {
                S[nf][0] = __expf(S[nf][0] - mn);
                S[nf][1] = __expf(S[nf][1] - mn);
                rs += S[nf][0] + S[nf][1];
            }
            rs += __shfl_xor_sync(0xffffffffu, rs, 1);
            rs += __shfl_xor_sync(0xffffffffu, rs, 2);
            l0 = l0 * alpha + rs;
#pragma unroll
            for (int nf = 0; nf < 8; nf++) { O[nf][0] *= alpha; O[nf][1] *= alpha; }
        }
        {
            float rm = -1e30f;
#pragma unroll
            for (int nf = 0; nf < 8; nf++) rm = fmaxf(rm, fmaxf(S[nf][2], S[nf][3]));
            rm = fmaxf(rm, __shfl_xor_sync(0xffffffffu, rm, 1));
            rm = fmaxf(rm, __shfl_xor_sync(0xffffffffu, rm, 2));
            float mn = fmaxf(m1, rm);
            float alpha = __expf(m1 - mn);
            m1 = mn;
            float rs = 0.f;
#pragma unroll
            for (int nf = 0; nf < 8; nf++) {
                S[nf][2] = __expf(S[nf][2] - mn);
                S[nf][3] = __expf(S[nf][3] - mn);
                rs += S[nf][2] + S[nf][3];
            }
            rs += __shfl_xor_sync(0xffffffffu, rs, 1);
            rs += __shfl_xor_sync(0xffffffffu, rs, 2);
            l1 = l1 * alpha + rs;
#pragma unroll
            for (int nf = 0; nf < 8; nf++) { O[nf][2] *= alpha; O[nf][3] *= alpha; }
        }

        {
            const int r0 = warp * 16 + g;
#pragma unroll
            for (int nf = 0; nf < 8; nf++) {
                int c = nf * 8 + qk * 2;
                float2 p0; p0.x = to_tf32(S[nf][0]); p0.y = to_tf32(S[nf][1]);
                float2 p1; p1.x = to_tf32(S[nf][2]); p1.y = to_tf32(S[nf][3]);
                *(float2*)&Ps[r0 * QS_STRIDE + c]       = p0;
                *(float2*)&Ps[(r0 + 8) * QS_STRIDE + c] = p1;
            }
        }
        __syncwarp();

#pragma unroll
        for (int ks = 0; ks < 8; ks++) {
            const int kc = ks * 8 + qk;
            const int r0 = warp * 16 + g;
            uint32_t a0 = f2u(Ps[r0 * QS_STRIDE + kc]);
            uint32_t a1 = f2u(Ps[(r0 + 8) * QS_STRIDE + kc]);
            uint32_t a2 = f2u(Ps[r0 * QS_STRIDE + kc + 4]);
            uint32_t a3 = f2u(Ps[(r0 + 8) * QS_STRIDE + kc + 4]);
#pragma unroll
            for (int nf = 0; nf < 8; nf++) {
                int n0 = nf * 8 + g;
                uint32_t b0 = f2u(Vs[kc * VS_STRIDE + n0]);
                uint32_t b1 = f2u(Vs[(kc + 4) * VS_STRIDE + n0]);
                mma_tf32(O[nf], a0, a1, a2, a3, b0, b1);
            }
        }
    }

    const float inv0 = 1.0f / l0, inv1 = 1.0f / l1;
    const int qr = q0 + warp * 16 + g;
    float* y0 = Y + ((size_t)b * Tn + qr) * Dm + h * 64;
    float* y1 = y0 + (size_t)8 * Dm;
#pragma unroll
    for (int nf = 0; nf < 8; nf++) {
        int c = nf * 8 + qk * 2;
        float2 v0; v0.x = to_tf32(O[nf][0] * inv0); v0.y = to_tf32(O[nf][1] * inv0);
        float2 v1; v1.x = to_tf32(O[nf][2] * inv1); v1.y = to_tf32(O[nf][3] * inv1);
        *(float2*)(y0 + c) = v0;
        *(float2*)(y1 + c) = v1;
    }
}

// ---------------- launch ----------------
extern "C" void kernel_launch(void* const* d_in, const int* in_sizes, int n_in,
                              void* d_out, int out_size)
{
    (void)in_sizes; (void)n_in; (void)out_size;
    const float* x     = (const float*)d_in[0];
    const float* Wqkv  = (const float*)d_in[1];
    const float* Wproj = (const float*)d_in[2];
    const float* Wfc1  = (const float*)d_in[3];
    const float* Wfc2  = (const float*)d_in[4];
    const float* ln1g  = (const float*)d_in[5];
    const float* ln1b  = (const float*)d_in[6];
    const float* ln2g  = (const float*)d_in[7];
    const float* ln2b  = (const float*)d_in[8];
    float* out = (float*)d_out;

    float *h, *qkv, *y, *x1, *a, *w;
    cudaGetSymbolAddress((void**)&h,   g_h);
    cudaGetSymbolAddress((void**)&qkv, g_qkv);
    cudaGetSymbolAddress((void**)&y,   g_y);
    cudaGetSymbolAddress((void**)&x1,  g_x1);
    cudaGetSymbolAddress((void**)&a,   g_a);
    cudaGetSymbolAddress((void**)&w,   g_w);

    cudaFuncSetAttribute(attn_mma, cudaFuncAttributeMaxDynamicSharedMemorySize, ATTN_SMEM_BYTES);
    cudaFuncSetAttribute(mma_gemm<0,0,0>, cudaFuncAttributeMaxDynamicSharedMemorySize, GEMM_SMEM_BYTES);
    cudaFuncSetAttribute(mma_gemm<0,1,0>, cudaFuncAttributeMaxDynamicSharedMemorySize, GEMM_SMEM_BYTES);
    cudaFuncSetAttribute(mma_gemm<1,0,1>, cudaFuncAttributeMaxDynamicSharedMemorySize, GEMM_SMEM_BYTES);

    // 0) convert weights to tf32 bit patterns
    cvt_kernel<<<512, 256>>>(Wqkv,  w + WQKV_OFF,  (int)((size_t)Dm * 3 * Dm / 4));
    cvt_kernel<<<512, 256>>>(Wproj, w + WPROJ_OFF, (int)((size_t)Dm * Dm / 4));
    cvt_kernel<<<512, 256>>>(Wfc1,  w + WFC1_OFF,  (int)((size_t)Dm * DFFn / 4));
    cvt_kernel<<<512, 256>>>(Wfc2,  w + WFC2_OFF,  (int)((size_t)DFFn * Dm / 4));

    // 1) ln1 (tf32-rounded)
    ln_kernel<<<Mrows, 256>>>(x, ln1g, ln1b, h);
    // 2) qkv = h @ W_qkv
    mma_gemm<0,0,0><<<dim3(3 * Dm / 128, Mrows / 128), 128, GEMM_SMEM_BYTES>>>(
        h, w + WQKV_OFF, nullptr, qkv, Mrows, 3 * Dm, Dm);
    // 3) attention (y tf32-rounded)
    attn_mma<<<dim3(Tn / 64, Hn, Bn), 128, ATTN_SMEM_BYTES>>>(qkv, y);
    // 4) x1 = x + y @ W_proj
    mma_gemm<0,1,0><<<dim3(Dm / 128, Mrows / 128), 128, GEMM_SMEM_BYTES>>>(
        y, w + WPROJ_OFF, x, x1, Mrows, Dm, Dm);
    // 5) ln2
    ln_kernel<<<Mrows, 256>>>(x1, ln2g, ln2b, h);
    // 6) a = tf32(gelu(h @ W_fc1))
    mma_gemm<1,0,1><<<dim3(DFFn / 128, Mrows / 128), 128, GEMM_SMEM_BYTES>>>(
        h, w + WFC1_OFF, nullptr, a, Mrows, DFFn, Dm);
    // 7) out = x1 + a @ W_fc2
    mma_gemm<0,1,0><<<dim3(Dm / 128, Mrows / 128), 128, GEMM_SMEM_BYTES>>>(
        a, w + WFC2_OFF, x1, out, Mrows, Dm, DFFn);
}

// round 11
// speedup vs baseline: 3.3589x; 1.0342x over previous
#include <cuda_runtime.h>
#include <math.h>
#include <stdint.h>

// ---------------- problem constants ----------------
#define Dm   1024
#define Tn   2048
#define Bn   2
#define Hn   16
#define DFFn 4096
#define Mrows (Bn * Tn)   // 4096

// ---------------- scratch (no allocation allowed) ----------------
__device__ float g_h  [(size_t)Mrows * Dm];
__device__ float g_qkv[(size_t)Mrows * 3 * Dm];
__device__ float g_y  [(size_t)Mrows * Dm];
__device__ float g_x1 [(size_t)Mrows * Dm];
__device__ float g_a  [(size_t)Mrows * DFFn];
// tf32-rounded weights (plain [K][N] layout): qkv | proj | fc1 | fc2
#define WQKV_OFF  0
#define WPROJ_OFF ((size_t)Dm * 3 * Dm)
#define WFC1_OFF  (WPROJ_OFF + (size_t)Dm * Dm)
#define WFC2_OFF  (WFC1_OFF + (size_t)Dm * DFFn)
#define W_TOTAL   (WFC2_OFF + (size_t)DFFn * Dm)
__device__ float g_w[W_TOTAL];

// ---------------- helpers ----------------
__device__ __forceinline__ float to_tf32(float x) {
    uint32_t u;
    asm("cvt.rna.tf32.f32 %0, %1;" : "=r"(u) : "f"(x));
    return __uint_as_float(u);
}
__device__ __forceinline__ uint32_t f2u(float x) { return __float_as_uint(x); }

__device__ __forceinline__ void mma_tf32(float* c,
                                         uint32_t a0, uint32_t a1, uint32_t a2, uint32_t a3,
                                         uint32_t b0, uint32_t b1) {
    asm volatile(
        "mma.sync.aligned.m16n8k8.row.col.f32.tf32.tf32.f32 "
        "{%0,%1,%2,%3}, {%4,%5,%6,%7}, {%8,%9}, {%0,%1,%2,%3};"
        : "+f"(c[0]), "+f"(c[1]), "+f"(c[2]), "+f"(c[3])
        : "r"(a0), "r"(a1), "r"(a2), "r"(a3), "r"(b0), "r"(b1));
}

__device__ __forceinline__ void cp16(uint32_t smem_addr, const void* gptr) {
    asm volatile("cp.async.cg.shared.global [%0], [%1], 16;"
                 :: "r"(smem_addr), "l"(gptr));
}
#define CP_COMMIT() asm volatile("cp.async.commit_group;")

__device__ __forceinline__ float gelu_exact(float x) {
    return 0.5f * x * (1.0f + erff(x * 0.70710678118654752f));
}

// ---------------- weight tf32 conversion (single launch) ----------------
__global__ void cvt_all(const float* __restrict__ wqkv, const float* __restrict__ wproj,
                        const float* __restrict__ wfc1, const float* __restrict__ wfc2,
                        float* __restrict__ w)
{
    const int tidg = blockIdx.x * blockDim.x + threadIdx.x;
    const int stride = gridDim.x * blockDim.x;
    const float4* srcs[4] = { (const float4*)wqkv, (const float4*)wproj,
                              (const float4*)wfc1, (const float4*)wfc2 };
    float4* dsts[4] = { (float4*)(w + WQKV_OFF), (float4*)(w + WPROJ_OFF),
                        (float4*)(w + WFC1_OFF), (float4*)(w + WFC2_OFF) };
    const int n4s[4] = { (int)((size_t)Dm * 3 * Dm / 4), (int)((size_t)Dm * Dm / 4),
                         (int)((size_t)Dm * DFFn / 4),   (int)((size_t)DFFn * Dm / 4) };
#pragma unroll
    for (int s = 0; s < 4; s++) {
        const float4* s4 = srcs[s];
        float4* d4 = dsts[s];
        int n4 = n4s[s];
        for (int j = tidg; j < n4; j += stride) {
            float4 v = s4[j];
            v.x = to_tf32(v.x); v.y = to_tf32(v.y);
            v.z = to_tf32(v.z); v.w = to_tf32(v.w);
            d4[j] = v;
        }
    }
}

// ---------------- LayerNorm (tf32-rounded output) ----------------
__global__ void ln_kernel(const float* __restrict__ X,
                          const float* __restrict__ gw,
                          const float* __restrict__ bw,
                          float* __restrict__ O)
{
    int row = blockIdx.x;
    int tid = threadIdx.x;
    const float4* xr = (const float4*)(X + (size_t)row * Dm);
    float4 v = xr[tid];
    float s  = v.x + v.y + v.z + v.w;
    float sq = v.x * v.x + v.y * v.y + v.z * v.z + v.w * v.w;
#pragma unroll
    for (int o = 16; o > 0; o >>= 1) {
        s  += __shfl_xor_sync(0xffffffffu, s,  o);
        sq += __shfl_xor_sync(0xffffffffu, sq, o);
    }
    __shared__ float ws[8], wq[8];
    int wid = tid >> 5, lane = tid & 31;
    if (lane == 0) { ws[wid] = s; wq[wid] = sq; }
    __syncthreads();
    float ts = 0.f, tq = 0.f;
#pragma unroll
    for (int i = 0; i < 8; i++) { ts += ws[i]; tq += wq[i]; }
    float mean = ts * (1.0f / Dm);
    float var  = tq * (1.0f / Dm) - mean * mean;
    float rstd = rsqrtf(var + 1e-5f);
    float4 g4 = ((const float4*)gw)[tid];
    float4 b4 = ((const float4*)bw)[tid];
    float4 o4;
    o4.x = to_tf32((v.x - mean) * rstd * g4.x + b4.x);
    o4.y = to_tf32((v.y - mean) * rstd * g4.y + b4.y);
    o4.z = to_tf32((v.z - mean) * rstd * g4.z + b4.z);
    o4.w = to_tf32((v.w - mean) * rstd * g4.w + b4.w);
    ((float4*)(O + (size_t)row * Dm))[tid] = o4;
}

// ---------------- TF32 GEMM, cp.async 4-stage, 4 warps, warp tile 64x64 ----------------
#define STAGES 4
#define AS_STRIDE 20
#define BS_STRIDE 136
#define AS_FLOATS (128 * AS_STRIDE)
#define BS_FLOATS (16 * BS_STRIDE)
#define STAGE_FLOATS (AS_FLOATS + BS_FLOATS)
#define GEMM_SMEM_BYTES (STAGES * STAGE_FLOATS * 4)

template <int GELU, int RESID, int ROUND>
__global__ __launch_bounds__(128, 2)
void mma_gemm(const float* __restrict__ A, const float* __restrict__ B,
              const float* __restrict__ R, float* __restrict__ C,
              int M, int N, int K)
{
    extern __shared__ float smf[];

    const int tid  = threadIdx.x;
    const int lane = tid & 31;
    const int warp = tid >> 5;      // 0..3
    const int wm = warp & 1;
    const int wn = warp >> 1;
    const int g  = lane >> 2;
    const int qk = lane & 3;
    const int bx = blockIdx.x, by = blockIdx.y;

    const float* Ag = A + (size_t)(by * 128) * K;
    const float* Bg = B + bx * 128;
    const uint32_t sbase = (uint32_t)__cvta_generic_to_shared(smf);

    float acc[4][8][4];
#pragma unroll
    for (int mf = 0; mf < 4; mf++)
#pragma unroll
        for (int nf = 0; nf < 8; nf++)
#pragma unroll
            for (int r = 0; r < 4; r++) acc[mf][nf][r] = 0.f;

    const int nIter = K / 16;

    auto fill = [&](int s, int ch) {
        uint32_t sA = sbase + (uint32_t)(s * STAGE_FLOATS * 4);
        uint32_t sB = sA + AS_FLOATS * 4;
        int k0 = ch * 16;
#pragma unroll
        for (int i = 0; i < 4; i++) {
            int idx = tid + i * 128;
            int r = idx >> 2, c = (idx & 3) * 4;
            cp16(sA + (uint32_t)((r * AS_STRIDE + c) * 4), Ag + (size_t)r * K + k0 + c);
        }
#pragma unroll
        for (int i = 0; i < 4; i++) {
            int idx = tid + i * 128;
            int r = idx >> 5, c = (idx & 31) * 4;
            cp16(sB + (uint32_t)((r * BS_STRIDE + c) * 4), Bg + (size_t)(k0 + r) * N + c);
        }
    };

#pragma unroll
    for (int s = 0; s < STAGES - 1; s++) { fill(s, s); CP_COMMIT(); }

    for (int it = 0; it < nIter; it++) {
        asm volatile("cp.async.wait_group %0;" :: "n"(STAGES - 2));
        __syncthreads();

        if (it + STAGES - 1 < nIter) fill((it + STAGES - 1) % STAGES, it + STAGES - 1);
        CP_COMMIT();

        const float* AsS = smf + (it % STAGES) * STAGE_FLOATS;
        const float* BsS = AsS + AS_FLOATS;

#pragma unroll
        for (int ks = 0; ks < 2; ks++) {
            const int kc = ks * 8 + qk;
            uint32_t af[4][4];
#pragma unroll
            for (int mf = 0; mf < 4; mf++) {
                int r0 = wm * 64 + mf * 16 + g;
                af[mf][0] = f2u(AsS[r0 * AS_STRIDE + kc]);
                af[mf][1] = f2u(AsS[(r0 + 8) * AS_STRIDE + kc]);
                af[mf][2] = f2u(AsS[r0 * AS_STRIDE + kc + 4]);
                af[mf][3] = f2u(AsS[(r0 + 8) * AS_STRIDE + kc + 4]);
            }
            uint32_t bf[8][2];
#pragma unroll
            for (int nf = 0; nf < 8; nf++) {
                int n0 = wn * 64 + nf * 8 + g;
                bf[nf][0] = f2u(BsS[kc * BS_STRIDE + n0]);
                bf[nf][1] = f2u(BsS[(kc + 4) * BS_STRIDE + n0]);
            }
#pragma unroll
            for (int mf = 0; mf < 4; mf++)
#pragma unroll
                for (int nf = 0; nf < 8; nf++)
                    mma_tf32(acc[mf][nf], af[mf][0], af[mf][1], af[mf][2], af[mf][3],
                             bf[nf][0], bf[nf][1]);
        }
    }

#pragma unroll
    for (int mf = 0; mf < 4; mf++) {
        int r0 = by * 128 + wm * 64 + mf * 16 + g;
#pragma unroll
        for (int nf = 0; nf < 8; nf++) {
            int c0 = bx * 128 + wn * 64 + nf * 8 + qk * 2;
            float2 v0, v1;
            v0.x = acc[mf][nf][0]; v0.y = acc[mf][nf][1];
            v1.x = acc[mf][nf][2]; v1.y = acc[mf][nf][3];
            if (GELU) {
                v0.x = gelu_exact(v0.x); v0.y = gelu_exact(v0.y);
                v1.x = gelu_exact(v1.x); v1.y = gelu_exact(v1.y);
            }
            if (RESID) {
                float2 r0v = *(const float2*)(R + (size_t)r0 * N + c0);
                float2 r1v = *(const float2*)(R + (size_t)(r0 + 8) * N + c0);
                v0.x += r0v.x; v0.y += r0v.y;
                v1.x += r1v.x; v1.y += r1v.y;
            }
            if (ROUND) {
                v0.x = to_tf32(v0.x); v0.y = to_tf32(v0.y);
                v1.x = to_tf32(v1.x); v1.y = to_tf32(v1.y);
            }
            *(float2*)(C + (size_t)r0 * N + c0)       = v0;
            *(float2*)(C + (size_t)(r0 + 8) * N + c0) = v1;
        }
    }
}

// ---------------- Flash attention: tf32 MMA + double-buffered cp.async K/V ----------------
// BQ=64, BK=64, hd=64, 4 warps. K/V stored raw fp32 (MMA truncates to tf32).
#define QS_STRIDE 68
#define VS_STRIDE 72
// floats: Qs 64*68 | Ks[2] 64*68 each | Ps 64*68 | Vs[2] 64*72 each
#define OFF_QS  0
#define OFF_KS0 (64 * QS_STRIDE)
#define OFF_KS1 (OFF_KS0 + 64 * QS_STRIDE)
#define OFF_PS  (OFF_KS1 + 64 * QS_STRIDE)
#define OFF_VS0 (OFF_PS + 64 * QS_STRIDE)
#define OFF_VS1 (OFF_VS0 + 64 * VS_STRIDE)
#define ATTN_SMEM_FLOATS (OFF_VS1 + 64 * VS_STRIDE)
#define ATTN_SMEM_BYTES (ATTN_SMEM_FLOATS * 4)

__global__ __launch_bounds__(128, 2)
void attn_mma(const float* __restrict__ QKV, float* __restrict__ Y)
{
    extern __shared__ float sm[];
    const uint32_t sbase = (uint32_t)__cvta_generic_to_shared(sm);

    const int tid  = threadIdx.x;
    const int lane = tid & 31;
    const int warp = tid >> 5;
    const int g  = lane >> 2;
    const int qk = lane & 3;

    const int qt = gridDim.x - 1 - blockIdx.x;   // heavy blocks first
    const int h  = blockIdx.y;
    const int b  = blockIdx.z;
    const int q0 = qt * 64;
    const int C3 = 3 * Dm;
    const float* base = QKV + (size_t)b * Tn * C3;

    // issue cp.async for K/V tile kt into buffer buf
    auto issueKV = [&](int buf, int kt) {
        const int k0 = kt * 64;
        const uint32_t koff = (buf ? OFF_KS1 : OFF_KS0);
        const uint32_t voff = (buf ? OFF_VS1 : OFF_VS0);
#pragma unroll
        for (int i = 0; i < 16; i++) {
            int idx = tid + i * 128;
            int r  = idx >> 4;          // 0..127 (K rows then V rows)
            int c  = (idx & 15) * 4;    // float offset in row
            if (r < 64) {
                const float* src = base + (size_t)(k0 + r) * C3 + 1024 + h * 64 + c;
                cp16(sbase + (uint32_t)((koff + r * QS_STRIDE + c) * 4), src);
            } else {
                int rv = r - 64;
                const float* src = base + (size_t)(k0 + rv) * C3 + 2048 + h * 64 + c;
                cp16(sbase + (uint32_t)((voff + rv * VS_STRIDE + c) * 4), src);
            }
        }
    };

    // prologue: start tile 0, load Q (scaled + tf32) meanwhile
    issueKV(0, 0);
    CP_COMMIT();

    float* Qs = sm + OFF_QS;
    float* Ps = sm + OFF_PS;
    for (int i = tid; i < 64 * 16; i += 128) {
        int r = i >> 4, c = (i & 15) * 4;
        float4 v = *(const float4*)(base + (size_t)(q0 + r) * C3 + h * 64 + c);
        Qs[r * QS_STRIDE + c + 0] = to_tf32(v.x * 0.125f);
        Qs[r * QS_STRIDE + c + 1] = to_tf32(v.y * 0.125f);
        Qs[r * QS_STRIDE + c + 2] = to_tf32(v.z * 0.125f);
        Qs[r * QS_STRIDE + c + 3] = to_tf32(v.w * 0.125f);
    }

    float O[8][4];
#pragma unroll
    for (int nf = 0; nf < 8; nf++)
#pragma unroll
        for (int r = 0; r < 4; r++) O[nf][r] = 0.f;
    float m0 = -1e30f, m1 = -1e30f, l0 = 0.f, l1 = 0.f;

    for (int kt = 0; kt <= qt; kt++) {
        asm volatile("cp.async.wait_group 0;");
        __syncthreads();   // tile kt resident; prior compute done

        if (kt < qt) { issueKV((kt + 1) & 1, kt + 1); }
        CP_COMMIT();

        const float* Ks = sm + ((kt & 1) ? OFF_KS1 : OFF_KS0);
        const float* Vs = sm + ((kt & 1) ? OFF_VS1 : OFF_VS0);

        // ---- S = Q @ K^T ----
        float S[8][4];
#pragma unroll
        for (int nf = 0; nf < 8; nf++)
#pragma unroll
            for (int r = 0; r < 4; r++) S[nf][r] = 0.f;

#pragma unroll
        for (int ks = 0; ks < 8; ks++) {
            const int kc = ks * 8 + qk;
            const int r0 = warp * 16 + g;
            uint32_t a0 = f2u(Qs[r0 * QS_STRIDE + kc]);
            uint32_t a1 = f2u(Qs[(r0 + 8) * QS_STRIDE + kc]);
            uint32_t a2 = f2u(Qs[r0 * QS_STRIDE + kc + 4]);
            uint32_t a3 = f2u(Qs[(r0 + 8) * QS_STRIDE + kc + 4]);
#pragma unroll
            for (int nf = 0; nf < 8; nf++) {
                int n0 = nf * 8 + g;
                uint32_t b0 = f2u(Ks[n0 * QS_STRIDE + kc]);
                uint32_t b1 = f2u(Ks[n0 * QS_STRIDE + kc + 4]);
                mma_tf32(S[nf], a0, a1, a2, a3, b0, b1);
            }
        }

        if (kt == qt) {   // causal mask on diagonal tile
            const int r0 = warp * 16 + g, r1 = r0 + 8;
#pragma unroll
            for (int nf = 0; nf < 8; nf++) {
                int c = nf * 8 + qk * 2;
                if (c     > r0) S[nf][0] = -1e30f;
                if (c + 1 > r0) S[nf][1] = -1e30f;
                if (c     > r1) S[nf][2] = -1e30f;
                if (c + 1 > r1) S[nf][3] = -1e30f;
            }
        }

        // ---- online softmax ----
        {
            float rm = -1e30f;
#pragma unroll
            for (int nf = 0; nf < 8; nf++) rm = fmaxf(rm, fmaxf(S[nf][0], S[nf][1]));
            rm = fmaxf(rm, __shfl_xor_sync(0xffffffffu, rm, 1));
            rm = fmaxf(rm, __shfl_xor_sync(0xffffffffu, rm, 2));
            float mn = fmaxf(m0, rm);
            float alpha = __expf(m0 - mn);
            m0 = mn;
            float rs = 0.f;
#pragma unroll
            for (int nf = 0; nf < 8; nf++) {
                S[nf][0] = __expf(S[nf][0] - mn);
                S[nf][1] = __expf(S[nf][1] - mn);
                rs += S[nf][0] + S[nf][1];
            }
            rs += __shfl_xor_sync(0xffffffffu, rs, 1);
            rs += __shfl_xor_sync(0xffffffffu, rs, 2);
            l0 = l0 * alpha + rs;
#pragma unroll
            for (int nf = 0; nf < 8; nf++) { O[nf][0] *= alpha; O[nf][1] *= alpha; }
        }
        {
            float rm = -1e30f;
#pragma unroll
            for (int nf = 0; nf < 8; nf++) rm = fmaxf(rm, fmaxf(S[nf][2], S[nf][3]));
            rm = fmaxf(rm, __shfl_xor_sync(0xffffffffu, rm, 1));
            rm = fmaxf(rm, __shfl_xor_sync(0xffffffffu, rm, 2));
            float mn = fmaxf(m1, rm);
            float alpha = __expf(m1 - mn);
            m1 = mn;
            float rs = 0.f;
#pragma unroll
            for (int nf = 0; nf < 8; nf++) {
                S[nf][2] = __expf(S[nf][2] - mn);
                S[nf][3] = __expf(S[nf][3] - mn);
                rs += S[nf][2] + S[nf][3];
            }
            rs += __shfl_xor_sync(0xffffffffu, rs, 1);
            rs += __shfl_xor_sync(0xffffffffu, rs, 2);
            l1 = l1 * alpha + rs;
#pragma unroll
            for (int nf = 0; nf < 8; nf++) { O[nf][2] *= alpha; O[nf][3] *= alpha; }
        }

        // ---- write P to warp-private Ps rows ----
        {
            const int r0 = warp * 16 + g;
#pragma unroll
            for (int nf = 0; nf < 8; nf++) {
                int c = nf * 8 + qk * 2;
                float2 p0; p0.x = S[nf][0]; p0.y = S[nf][1];
                float2 p1; p1.x = S[nf][2]; p1.y = S[nf][3];
                *(float2*)&Ps[r0 * QS_STRIDE + c]       = p0;
                *(float2*)&Ps[(r0 + 8) * QS_STRIDE + c] = p1;
            }
        }
        __syncwarp();

        // ---- O += P @ V ----
#pragma unroll
        for (int ks = 0; ks < 8; ks++) {
            const int kc = ks * 8 + qk;
            const int r0 = warp * 16 + g;
            uint32_t a0 = f2u(Ps[r0 * QS_STRIDE + kc]);
            uint32_t a1 = f2u(Ps[(r0 + 8) * QS_STRIDE + kc]);
            uint32_t a2 = f2u(Ps[r0 * QS_STRIDE + kc + 4]);
            uint32_t a3 = f2u(Ps[(r0 + 8) * QS_STRIDE + kc + 4]);
#pragma unroll
            for (int nf = 0; nf < 8; nf++) {
                int n0 = nf * 8 + g;
                uint32_t b0 = f2u(Vs[kc * VS_STRIDE + n0]);
                uint32_t b1 = f2u(Vs[(kc + 4) * VS_STRIDE + n0]);
                mma_tf32(O[nf], a0, a1, a2, a3, b0, b1);
            }
        }
    }

    const float inv0 = 1.0f / l0, inv1 = 1.0f / l1;
    const int qr = q0 + warp * 16 + g;
    float* y0 = Y + ((size_t)b * Tn + qr) * Dm + h * 64;
    float* y1 = y0 + (size_t)8 * Dm;
#pragma unroll
    for (int nf = 0; nf < 8; nf++) {
        int c = nf * 8 + qk * 2;
        float2 v0; v0.x = to_tf32(O[nf][0] * inv0); v0.y = to_tf32(O[nf][1] * inv0);
        float2 v1; v1.x = to_tf32(O[nf][2] * inv1); v1.y = to_tf32(O[nf][3] * inv1);
        *(float2*)(y0 + c) = v0;
        *(float2*)(y1 + c) = v1;
    }
}

// ---------------- launch ----------------
extern "C" void kernel_launch(void* const* d_in, const int* in_sizes, int n_in,
                              void* d_out, int out_size)
{
    (void)in_sizes; (void)n_in; (void)out_size;
    const float* x     = (const float*)d_in[0];
    const float* Wqkv  = (const float*)d_in[1];
    const float* Wproj = (const float*)d_in[2];
    const float* Wfc1  = (const float*)d_in[3];
    const float* Wfc2  = (const float*)d_in[4];
    const float* ln1g  = (const float*)d_in[5];
    const float* ln1b  = (const float*)d_in[6];
    const float* ln2g  = (const float*)d_in[7];
    const float* ln2b  = (const float*)d_in[8];
    float* out = (float*)d_out;

    float *h, *qkv, *y, *x1, *a, *w;
    cudaGetSymbolAddress((void**)&h,   g_h);
    cudaGetSymbolAddress((void**)&qkv, g_qkv);
    cudaGetSymbolAddress((void**)&y,   g_y);
    cudaGetSymbolAddress((void**)&x1,  g_x1);
    cudaGetSymbolAddress((void**)&a,   g_a);
    cudaGetSymbolAddress((void**)&w,   g_w);

    cudaFuncSetAttribute(attn_mma, cudaFuncAttributeMaxDynamicSharedMemorySize, ATTN_SMEM_BYTES);
    cudaFuncSetAttribute(mma_gemm<0,0,0>, cudaFuncAttributeMaxDynamicSharedMemorySize, GEMM_SMEM_BYTES);
    cudaFuncSetAttribute(mma_gemm<0,1,0>, cudaFuncAttributeMaxDynamicSharedMemorySize, GEMM_SMEM_BYTES);
    cudaFuncSetAttribute(mma_gemm<1,0,1>, cudaFuncAttributeMaxDynamicSharedMemorySize, GEMM_SMEM_BYTES);

    // 0) convert all weights to tf32 (one launch)
    cvt_all<<<1024, 256>>>(Wqkv, Wproj, Wfc1, Wfc2, w);

    // 1) ln1 (tf32-rounded)
    ln_kernel<<<Mrows, 256>>>(x, ln1g, ln1b, h);
    // 2) qkv = h @ W_qkv
    mma_gemm<0,0,0><<<dim3(3 * Dm / 128, Mrows / 128), 128, GEMM_SMEM_BYTES>>>(
        h, w + WQKV_OFF, nullptr, qkv, Mrows, 3 * Dm, Dm);
    // 3) attention (y tf32-rounded)
    attn_mma<<<dim3(Tn / 64, Hn, Bn), 128, ATTN_SMEM_BYTES>>>(qkv, y);
    // 4) x1 = x + y @ W_proj
    mma_gemm<0,1,0><<<dim3(Dm / 128, Mrows / 128), 128, GEMM_SMEM_BYTES>>>(
        y, w + WPROJ_OFF, x, x1, Mrows, Dm, Dm);
    // 5) ln2
    ln_kernel<<<Mrows, 256>>>(x1, ln2g, ln2b, h);
    // 6) a = tf32(gelu(h @ W_fc1))
    mma_gemm<1,0,1><<<dim3(DFFn / 128, Mrows / 128), 128, GEMM_SMEM_BYTES>>>(
        h, w + WFC1_OFF, nullptr, a, Mrows, DFFn, Dm);
    // 7) out = x1 + a @ W_fc2
    mma_gemm<0,1,0><<<dim3(Dm / 128, Mrows / 128), 128, GEMM_SMEM_BYTES>>>(
        a, w + WFC2_OFF, x1, out, Mrows, Dm, DFFn);
}